// round 1
// baseline (speedup 1.0000x reference)
#include <cuda_runtime.h>
#include <math.h>

// ---------------------------------------------------------------------------
// Problem constants
//   hidden_states        (8, 4096, 1280)  f32
//   encoder_hidden_states(8, 81, 2048)    f32   (77 text rows + 4 ip rows)
//   w_q (1280,1280)  w_k/w_v/w_k_ip/w_v_ip (2048,1280)  w_out (1280,1280)
//   b_out (1280,)    heads = 8 (D = 160)
//   out (8, 4096, 1280) f32
// ---------------------------------------------------------------------------
#define BATCH   8
#define SEQ     4096
#define HS      1280
#define HEADS   8
#define DH      160
#define DP      161          // padded row stride in smem (conflict-free)
#define NKEY    77
#define NIP     4
#define CROSSD  2048
#define MQ      (BATCH*SEQ)  // 32768 rows

// Scratch (device globals: the sanctioned allocation-free workaround)
__device__ float g_Q[MQ * HS];        // 167 MB
__device__ float g_Attn[MQ * HS];     // 167 MB
__device__ float g_K[BATCH * NKEY * HS];
__device__ float g_V[BATCH * NKEY * HS];
__device__ float g_Kip[BATCH * NIP * HS];
__device__ float g_Vip[BATCH * NIP * HS];

// ---------------------------------------------------------------------------
// Register-tiled fp32 GEMM:  C[M,N] = A[M,K] @ B[K,N] (+bias)
// GATHER: logical A-row r -> physical row (r/rows_used)*rows_total + row_off + r%rows_used
// Requires: K % BK == 0, N % BN == 0 (holds for all launches here).
// ---------------------------------------------------------------------------
template<int BM,int BN,int BK,int TM,int TN,bool GATHER,bool BIAS>
__global__ void __launch_bounds__((BM/TM)*(BN/TN), 2)
gemm_k(const float* __restrict__ A, const float* __restrict__ Bw,
       const float* __restrict__ bias, float* __restrict__ C,
       int M, int N, int K,
       int rows_used, int rows_total, int row_off)
{
    constexpr int NT   = (BM/TM)*(BN/TN);
    constexpr int ASTR = BM + 4;
    constexpr int K4   = BK/4;
    constexpr int LA   = (BM*BK)/(4*NT);
    constexpr int LB   = (BK*BN)/(4*NT);

    __shared__ float As[BK*ASTR];
    __shared__ float Bs[BK*BN];

    const int t  = threadIdx.x;
    const int bm = blockIdx.y * BM;
    const int bn = blockIdx.x * BN;

    int  a_m[LA], a_k4[LA];
    long a_base[LA];
    bool a_ok[LA];
#pragma unroll
    for (int i = 0; i < LA; i++) {
        int f   = t + i*NT;
        a_m[i]  = f / K4;
        a_k4[i] = f % K4;
        int gr  = bm + a_m[i];
        a_ok[i] = (gr < M);
        int pr  = gr;
        if (GATHER) pr = (gr / rows_used) * rows_total + row_off + (gr % rows_used);
        a_base[i] = (long)(a_ok[i] ? pr : 0) * K;
    }
    int b_k[LB], b_n4[LB];
#pragma unroll
    for (int i = 0; i < LB; i++) {
        int f    = t + i*NT;
        b_k[i]   = f / (BN/4);
        b_n4[i]  = f % (BN/4);
    }

    const int rowg = (t / (BN/TN)) * TM;
    const int colg = (t % (BN/TN)) * TN;

    float acc[TM][TN];
#pragma unroll
    for (int i = 0; i < TM; i++)
#pragma unroll
        for (int j = 0; j < TN; j++) acc[i][j] = 0.f;

    const int nkt = K / BK;
    float4 ar[LA], br[LB];

    auto loadg = [&](int kt) {
#pragma unroll
        for (int i = 0; i < LA; i++) {
            if (a_ok[i])
                ar[i] = *(const float4*)(A + a_base[i] + (long)kt*BK + a_k4[i]*4);
            else
                ar[i] = make_float4(0.f, 0.f, 0.f, 0.f);
        }
#pragma unroll
        for (int i = 0; i < LB; i++)
            br[i] = *(const float4*)(Bw + (long)(kt*BK + b_k[i])*N + bn + b_n4[i]*4);
    };
    auto store_s = [&]() {
#pragma unroll
        for (int i = 0; i < LA; i++) {
            As[(a_k4[i]*4 + 0)*ASTR + a_m[i]] = ar[i].x;
            As[(a_k4[i]*4 + 1)*ASTR + a_m[i]] = ar[i].y;
            As[(a_k4[i]*4 + 2)*ASTR + a_m[i]] = ar[i].z;
            As[(a_k4[i]*4 + 3)*ASTR + a_m[i]] = ar[i].w;
        }
#pragma unroll
        for (int i = 0; i < LB; i++)
            *(float4*)(&Bs[b_k[i]*BN + b_n4[i]*4]) = br[i];
    };

    loadg(0);
    store_s();
    __syncthreads();

    for (int kt = 0; kt < nkt; kt++) {
        if (kt + 1 < nkt) loadg(kt + 1);
#pragma unroll
        for (int k = 0; k < BK; k++) {
            float a[TM], b[TN];
#pragma unroll
            for (int i = 0; i < TM; i++) a[i] = As[k*ASTR + rowg + i];
#pragma unroll
            for (int j = 0; j < TN; j++) b[j] = Bs[k*BN + colg + j];
#pragma unroll
            for (int i = 0; i < TM; i++)
#pragma unroll
                for (int j = 0; j < TN; j++)
                    acc[i][j] += a[i] * b[j];
        }
        __syncthreads();
        if (kt + 1 < nkt) { store_s(); __syncthreads(); }
    }

#pragma unroll
    for (int i = 0; i < TM; i++) {
        int gr = bm + rowg + i;
        if (gr >= M) continue;
#pragma unroll
        for (int j = 0; j < TN; j += 4) {
            int gc = bn + colg + j;
            float4 v;
            v.x = acc[i][j+0]; v.y = acc[i][j+1]; v.z = acc[i][j+2]; v.w = acc[i][j+3];
            if (BIAS) {
                v.x += bias[gc+0]; v.y += bias[gc+1];
                v.z += bias[gc+2]; v.w += bias[gc+3];
            }
            *(float4*)(C + (long)gr*N + gc) = v;
        }
    }
}

// ---------------------------------------------------------------------------
// Fused dual attention (text keys + ip keys, separate softmaxes).
// grid = (SEQ/CHQ, HEADS, BATCH), 256 threads (8 warps).
// Each warp processes 2 queries per pass:
//   - lane-per-key score phase (q broadcast via shfl, K from smem)
//   - warp-reduced softmax over 77 text keys; tiny 4-key ip softmax
//   - lane-per-d-column PV accumulation
// ---------------------------------------------------------------------------
#define CHQ      512
#define AT_WARPS 8
#define PS_STR   96

__global__ void __launch_bounds__(256, 2)
attn_k(const float* __restrict__ Q, const float* __restrict__ K,
       const float* __restrict__ V, const float* __restrict__ Kip,
       const float* __restrict__ Vip, float* __restrict__ O)
{
    extern __shared__ float sm[];
    float* Ks  = sm;                       // NKEY*DP
    float* Vs  = Ks  + NKEY*DP;            // NKEY*DP
    float* Kis = Vs  + NKEY*DP;            // NIP*DP
    float* Vis = Kis + NIP*DP;             // NIP*DP
    float* Ps  = Vis + NIP*DP;             // AT_WARPS*2*PS_STR
    float* Pip = Ps  + AT_WARPS*2*PS_STR;  // AT_WARPS*2*NIP

    const int b    = blockIdx.z;
    const int h    = blockIdx.y;
    const int ch   = blockIdx.x;
    const int tid  = threadIdx.x;
    const int w    = tid >> 5;
    const int lane = tid & 31;

    // cooperative K/V loads into smem (padded rows)
    for (int idx = tid; idx < NKEY*DH; idx += 256) {
        int s = idx / DH, d = idx % DH;
        long src = (long)(b*NKEY + s)*HS + h*DH + d;
        Ks[s*DP + d] = K[src];
        Vs[s*DP + d] = V[src];
    }
    for (int idx = tid; idx < NIP*DH; idx += 256) {
        int s = idx / DH, d = idx % DH;
        long src = (long)(b*NIP + s)*HS + h*DH + d;
        Kis[s*DP + d] = Kip[src];
        Vis[s*DP + d] = Vip[src];
    }
    __syncthreads();

    const float scale = 0.07905694150420949f;  // 1/sqrt(160)

    int  krow[3]; bool kval[3];
#pragma unroll
    for (int j = 0; j < 3; j++) {
        int s   = lane + 32*j;
        kval[j] = (s < NKEY);
        krow[j] = (kval[j] ? s : 0) * DP;
    }
    const int iprow = (lane < NIP ? lane : 0) * DP;

    for (int qp = w; qp < CHQ/2; qp += AT_WARPS) {
        const int  q0 = ch*CHQ + qp*2;                    // per-batch query idx
        const long r0 = ((long)b*SEQ + q0)*HS + h*DH;

        float qv0[5], qv1[5];
#pragma unroll
        for (int i = 0; i < 5; i++) {
            qv0[i] = Q[r0 +      lane + 32*i];
            qv1[i] = Q[r0 + HS + lane + 32*i];
        }

        float sc0[3] = {0.f,0.f,0.f}, sc1[3] = {0.f,0.f,0.f};
        float si0 = 0.f, si1 = 0.f;
#pragma unroll
        for (int i = 0; i < 5; i++) {
            float a0 = qv0[i], a1 = qv1[i];
#pragma unroll 8
            for (int dd = 0; dd < 32; dd++) {
                float qd0 = __shfl_sync(0xffffffffu, a0, dd);
                float qd1 = __shfl_sync(0xffffffffu, a1, dd);
                const float* kp = Ks + i*32 + dd;
                float k0 = kp[krow[0]], k1 = kp[krow[1]], k2 = kp[krow[2]];
                sc0[0] += qd0*k0; sc0[1] += qd0*k1; sc0[2] += qd0*k2;
                sc1[0] += qd1*k0; sc1[1] += qd1*k1; sc1[2] += qd1*k2;
                float kiv = Kis[iprow + i*32 + dd];
                si0 += qd0*kiv; si1 += qd1*kiv;
            }
        }

        // ---- text softmax (warp-wide over 77 keys) ----
        float m0 = -1e30f, m1 = -1e30f;
#pragma unroll
        for (int j = 0; j < 3; j++) {
            sc0[j] = kval[j] ? sc0[j]*scale : -1e30f;
            sc1[j] = kval[j] ? sc1[j]*scale : -1e30f;
            m0 = fmaxf(m0, sc0[j]);
            m1 = fmaxf(m1, sc1[j]);
        }
#pragma unroll
        for (int off = 16; off >= 1; off >>= 1) {
            m0 = fmaxf(m0, __shfl_xor_sync(0xffffffffu, m0, off));
            m1 = fmaxf(m1, __shfl_xor_sync(0xffffffffu, m1, off));
        }
        float e0[3], e1[3], s0 = 0.f, s1 = 0.f;
#pragma unroll
        for (int j = 0; j < 3; j++) {
            e0[j] = __expf(sc0[j] - m0); s0 += e0[j];
            e1[j] = __expf(sc1[j] - m1); s1 += e1[j];
        }
#pragma unroll
        for (int off = 16; off >= 1; off >>= 1) {
            s0 += __shfl_xor_sync(0xffffffffu, s0, off);
            s1 += __shfl_xor_sync(0xffffffffu, s1, off);
        }
        const float inv0 = 1.f / s0, inv1 = 1.f / s1;

        __syncwarp();
        float* Prow0 = Ps + (w*2 + 0)*PS_STR;
        float* Prow1 = Ps + (w*2 + 1)*PS_STR;
#pragma unroll
        for (int j = 0; j < 3; j++) {
            Prow0[lane + 32*j] = e0[j] * inv0;   // invalid keys -> 0 (exp underflow)
            Prow1[lane + 32*j] = e1[j] * inv1;
        }
        if (lane < NIP) {
            Pip[(w*2 + 0)*NIP + lane] = si0 * scale;
            Pip[(w*2 + 1)*NIP + lane] = si1 * scale;
        }
        __syncwarp();

        // ---- ip softmax (4 keys, computed redundantly per lane) ----
        float pi0[NIP], pi1[NIP];
        {
            float mm0 = -1e30f, mm1 = -1e30f;
#pragma unroll
            for (int s = 0; s < NIP; s++) {
                pi0[s] = Pip[(w*2 + 0)*NIP + s]; mm0 = fmaxf(mm0, pi0[s]);
                pi1[s] = Pip[(w*2 + 1)*NIP + s]; mm1 = fmaxf(mm1, pi1[s]);
            }
            float ss0 = 0.f, ss1 = 0.f;
#pragma unroll
            for (int s = 0; s < NIP; s++) {
                pi0[s] = __expf(pi0[s] - mm0); ss0 += pi0[s];
                pi1[s] = __expf(pi1[s] - mm1); ss1 += pi1[s];
            }
            float is0 = 1.f/ss0, is1 = 1.f/ss1;
#pragma unroll
            for (int s = 0; s < NIP; s++) { pi0[s] *= is0; pi1[s] *= is1; }
        }

        // ---- PV: lane owns d columns lane, lane+32, ... ----
        float o0[5] = {0.f,0.f,0.f,0.f,0.f};
        float o1[5] = {0.f,0.f,0.f,0.f,0.f};
        for (int s = 0; s < NKEY; s++) {
            float p0 = Prow0[s], p1 = Prow1[s];
            const float* vp = Vs + s*DP + lane;
#pragma unroll
            for (int i = 0; i < 5; i++) {
                float v = vp[32*i];
                o0[i] += p0 * v;
                o1[i] += p1 * v;
            }
        }
#pragma unroll
        for (int s = 0; s < NIP; s++) {
            const float* vp = Vis + s*DP + lane;
#pragma unroll
            for (int i = 0; i < 5; i++) {
                float v = vp[32*i];
                o0[i] += pi0[s] * v;
                o1[i] += pi1[s] * v;
            }
        }
#pragma unroll
        for (int i = 0; i < 5; i++) {
            O[r0 +      lane + 32*i] = o0[i];
            O[r0 + HS + lane + 32*i] = o1[i];
        }
        __syncwarp();
    }
}

// ---------------------------------------------------------------------------
// Launch
// ---------------------------------------------------------------------------
static const int ATT_SMEM =
    (2*NKEY*DP + 2*NIP*DP + AT_WARPS*2*PS_STR + AT_WARPS*2*NIP) * (int)sizeof(float);

extern "C" void kernel_launch(void* const* d_in, const int* in_sizes, int n_in,
                              void* d_out, int out_size)
{
    const float* hs   = (const float*)d_in[0];
    const float* ehs  = (const float*)d_in[1];
    const float* w_q  = (const float*)d_in[2];
    const float* w_k  = (const float*)d_in[3];
    const float* w_v  = (const float*)d_in[4];
    const float* w_ki = (const float*)d_in[5];
    const float* w_vi = (const float*)d_in[6];
    const float* w_o  = (const float*)d_in[7];
    const float* b_o  = (const float*)d_in[8];
    float* out = (float*)d_out;

    float *Qb, *Kb, *Vb, *Kib, *Vib, *Ab;
    cudaGetSymbolAddress((void**)&Qb,  g_Q);
    cudaGetSymbolAddress((void**)&Kb,  g_K);
    cudaGetSymbolAddress((void**)&Vb,  g_V);
    cudaGetSymbolAddress((void**)&Kib, g_Kip);
    cudaGetSymbolAddress((void**)&Vib, g_Vip);
    cudaGetSymbolAddress((void**)&Ab,  g_Attn);

    cudaFuncSetAttribute(attn_k, cudaFuncAttributeMaxDynamicSharedMemorySize, ATT_SMEM);

    // Q projection: 32768 x 1280 x 1280
    dim3 gq(HS/128, MQ/128);
    gemm_k<128,128,16,8,8,false,false><<<gq, 256>>>(hs, w_q, nullptr, Qb,
                                                    MQ, HS, HS, 1, 1, 0);

    // K/V projections: 616 x 1280 x 2048 (gather 77-of-81 rows per batch)
    dim3 gkv(HS/64, (BATCH*NKEY + 63)/64);
    gemm_k<64,64,16,4,4,true,false><<<gkv, 256>>>(ehs, w_k, nullptr, Kb,
                                                  BATCH*NKEY, HS, CROSSD, NKEY, 81, 0);
    gemm_k<64,64,16,4,4,true,false><<<gkv, 256>>>(ehs, w_v, nullptr, Vb,
                                                  BATCH*NKEY, HS, CROSSD, NKEY, 81, 0);

    // ip K/V projections: 32 x 1280 x 2048 (gather last 4 rows per batch)
    dim3 gip(HS/64, 1);
    gemm_k<64,64,16,4,4,true,false><<<gip, 256>>>(ehs, w_ki, nullptr, Kib,
                                                  BATCH*NIP, HS, CROSSD, NIP, 81, NKEY);
    gemm_k<64,64,16,4,4,true,false><<<gip, 256>>>(ehs, w_vi, nullptr, Vib,
                                                  BATCH*NIP, HS, CROSSD, NIP, 81, NKEY);

    // fused dual attention
    dim3 ga(SEQ/CHQ, HEADS, BATCH);
    attn_k<<<ga, 256, ATT_SMEM>>>(Qb, Kb, Vb, Kib, Vib, Ab);

    // output projection + bias: 32768 x 1280 x 1280
    gemm_k<128,128,16,8,8,false,true><<<gq, 256>>>(Ab, w_o, b_o, out,
                                                   MQ, HS, HS, 1, 1, 0);
}

// round 7
// speedup vs baseline: 1.7785x; 1.7785x over previous
#include <cuda.h>
#include <cuda_runtime.h>
#include <cuda_bf16.h>
#include <math.h>
#include <stdint.h>

// ---------------------------------------------------------------------------
// Problem constants
// ---------------------------------------------------------------------------
#define BATCH   8
#define SEQ     4096
#define HS      1280
#define HEADS   8
#define DH      160
#define DP      161
#define NKEY    77
#define NIP     4
#define CROSSD  2048
#define MQ      (BATCH*SEQ)      // 32768
#define KP      (3*HS)           // 3840  (hi | hi | lo packed K)

// Scratch device globals (allocation-free workaround)
__device__ float g_Q[MQ * HS];
__device__ float g_Attn[MQ * HS];
__device__ float g_K[BATCH * NKEY * HS];
__device__ float g_V[BATCH * NKEY * HS];
__device__ float g_Kip[BATCH * NIP * HS];
__device__ float g_Vip[BATCH * NIP * HS];
__device__ __nv_bfloat16 g_Ab[(size_t)MQ * KP];   // packed activations (hi|hi|lo)
__device__ __nv_bfloat16 g_Wb[(size_t)HS * KP];   // packed weight^T    (hi|lo|hi)

// ---------------------------------------------------------------------------
// Portable tensor-core GEMM (mma.sync bf16, cp.async, ldmatrix — sm_80+ ISA)
// C[M,N](f32) = A'[M,KP] @ B'[N,KP]^T
// CTA tile 128x128, K chunk 64 bf16 (128B SW128-swizzled rows), 4-stage pipe.
// ---------------------------------------------------------------------------
#define ST    4
#define KC    64
#define NCH   (KP/KC)              // 60
#define TSTG  16384                // one 128x64 bf16 tile
#define MMA_SMEM (1024 + ST*2*TSTG)

__device__ __forceinline__ uint32_t smem_u32(const void* p) {
    uint32_t a;
    asm("{ .reg .u64 t; cvta.to.shared.u64 t, %1; cvt.u32.u64 %0, t; }"
        : "=r"(a) : "l"(p));
    return a;
}

#define CP_ASYNC16(dst, src) \
    asm volatile("cp.async.cg.shared.global [%0], [%1], 16;" \
        :: "r"(dst), "l"(src) : "memory")
#define CP_COMMIT() asm volatile("cp.async.commit_group;" ::: "memory")
#define CP_WAIT(n)  asm volatile("cp.async.wait_group %0;" :: "n"(n) : "memory")

#define LDSM4(r, addr) \
    asm volatile("ldmatrix.sync.aligned.m8n8.x4.shared.b16 {%0,%1,%2,%3}, [%4];" \
        : "=r"((r)[0]), "=r"((r)[1]), "=r"((r)[2]), "=r"((r)[3]) : "r"(addr))

#define MMA16816(d, a, b0, b1) \
    asm volatile("mma.sync.aligned.m16n8k16.row.col.f32.bf16.bf16.f32 " \
        "{%0,%1,%2,%3}, {%4,%5,%6,%7}, {%8,%9}, {%0,%1,%2,%3};" \
        : "+f"((d)[0]), "+f"((d)[1]), "+f"((d)[2]), "+f"((d)[3]) \
        : "r"((a)[0]), "r"((a)[1]), "r"((a)[2]), "r"((a)[3]), "r"(b0), "r"(b1))

template<bool BIAS>
__global__ void __launch_bounds__(256, 1)
mma_gemm(const __nv_bfloat16* __restrict__ Ag, const __nv_bfloat16* __restrict__ Bg,
         const float* __restrict__ bias, float* __restrict__ C, int N)
{
    extern __shared__ char dsm[];
    const uint32_t sb = (smem_u32(dsm) + 1023u) & ~1023u;
    const int tid  = threadIdx.x;
    const int lane = tid & 31;
    const int wid  = tid >> 5;
    const int wm   = wid >> 2;        // 0..1  (64-row slab)
    const int wn   = wid & 3;         // 0..3  (32-col slab)
    const int mt   = blockIdx.y, nt = blockIdx.x;

    const __nv_bfloat16* Abase = Ag + (size_t)(mt*128) * KP;
    const __nv_bfloat16* Bbase = Bg + (size_t)(nt*128) * KP;

    // cp.async loader: 4 x 16B per thread per tile (1024 chunks / 256 thr)
    int ld_row[4], ld_sw[4];
#pragma unroll
    for (int i = 0; i < 4; i++) {
        int idx   = tid + i*256;
        ld_row[i] = idx >> 3;
        int c     = idx & 7;
        ld_sw[i]  = (c ^ (ld_row[i] & 7)) << 4;
    }

    auto load_chunk = [&](int ck, int st) {
        const uint32_t as = sb + st*TSTG;
        const uint32_t bs = sb + ST*TSTG + st*TSTG;
        const __nv_bfloat16* Ac = Abase + ck*KC;
        const __nv_bfloat16* Bc = Bbase + ck*KC;
#pragma unroll
        for (int i = 0; i < 4; i++) {
            int idx = tid + i*256;
            CP_ASYNC16(as + ld_row[i]*128 + ld_sw[i],
                       Ac + (size_t)ld_row[i]*KP + (idx & 7)*8);
        }
#pragma unroll
        for (int i = 0; i < 4; i++) {
            int idx = tid + i*256;
            CP_ASYNC16(bs + ld_row[i]*128 + ld_sw[i],
                       Bc + (size_t)ld_row[i]*KP + (idx & 7)*8);
        }
    };

    float acc[4][4][4];
#pragma unroll
    for (int mi = 0; mi < 4; mi++)
#pragma unroll
        for (int ni = 0; ni < 4; ni++)
#pragma unroll
            for (int j = 0; j < 4; j++) acc[mi][ni][j] = 0.f;

    // precomputed ldmatrix lane addressing (row byte-offset + swizzle key)
    const int a_row  = wm*64 + (lane & 15);          // + mi*16
    const int b_row  = wn*32 + ((lane >> 3) >> 1)*8 + (lane & 7);  // + p*16
    const int a_coff = lane >> 4;                    // k-half from lane
    const int b_coff = (lane >> 3) & 1;

    // prologue: fill ST-1 stages
#pragma unroll
    for (int s = 0; s < ST-1; s++) { load_chunk(s, s); CP_COMMIT(); }

    for (int ck = 0; ck < NCH; ck++) {
        CP_WAIT(ST-2);
        __syncthreads();

        int nk = ck + ST - 1;
        if (nk < NCH) load_chunk(nk, nk & (ST-1));
        CP_COMMIT();

        const int st = ck & (ST-1);
        const uint32_t as = sb + st*TSTG;
        const uint32_t bs = sb + ST*TSTG + st*TSTG;

#pragma unroll
        for (int ks = 0; ks < 4; ks++) {
            uint32_t afr[4][4], bfr[2][4];
#pragma unroll
            for (int mi = 0; mi < 4; mi++) {
                int row = a_row + mi*16;
                int c   = ks*2 + a_coff;
                LDSM4(afr[mi], as + row*128 + ((c ^ (row & 7)) << 4));
            }
#pragma unroll
            for (int p = 0; p < 2; p++) {
                int row = b_row + p*16;
                int c   = ks*2 + b_coff;
                LDSM4(bfr[p], bs + row*128 + ((c ^ (row & 7)) << 4));
            }
#pragma unroll
            for (int mi = 0; mi < 4; mi++)
#pragma unroll
                for (int ni = 0; ni < 4; ni++)
                    MMA16816(acc[mi][ni], afr[mi],
                             bfr[ni >> 1][(ni & 1)*2], bfr[ni >> 1][(ni & 1)*2 + 1]);
        }
        __syncthreads();
    }

    // epilogue: registers -> gmem fp32
    const int g  = lane >> 2, tq = lane & 3;
#pragma unroll
    for (int mi = 0; mi < 4; mi++) {
#pragma unroll
        for (int ni = 0; ni < 4; ni++) {
            int row0 = mt*128 + wm*64 + mi*16 + g;
            int col  = nt*128 + wn*32 + ni*8 + tq*2;
            float bx = 0.f, by = 0.f;
            if (BIAS) { bx = bias[col]; by = bias[col+1]; }
            float2 v0 = { acc[mi][ni][0] + bx, acc[mi][ni][1] + by };
            float2 v1 = { acc[mi][ni][2] + bx, acc[mi][ni][3] + by };
            *(float2*)(C + (size_t)row0 * N + col)     = v0;
            *(float2*)(C + (size_t)(row0+8) * N + col) = v1;
        }
    }
}

// ---------------------------------------------------------------------------
// fp32 -> packed bf16 split conversions
// activations: Y[m, 0:K]=hi, [K:2K]=hi, [2K:3K]=lo
// ---------------------------------------------------------------------------
__global__ void conv_act(const float* __restrict__ X, __nv_bfloat16* __restrict__ Y,
                         int M, int K)
{
    size_t i = (size_t)blockIdx.x * blockDim.x + threadIdx.x;
    size_t tot = (size_t)M * (K/4);
    if (i >= tot) return;
    size_t m = i / (K/4); int k4 = (int)(i % (K/4)) * 4;
    float4 v = reinterpret_cast<const float4*>(X)[i];
    __nv_bfloat16 h0 = __float2bfloat16_rn(v.x), h1 = __float2bfloat16_rn(v.y);
    __nv_bfloat16 h2 = __float2bfloat16_rn(v.z), h3 = __float2bfloat16_rn(v.w);
    __nv_bfloat16 l0 = __float2bfloat16_rn(v.x - __bfloat162float(h0));
    __nv_bfloat16 l1 = __float2bfloat16_rn(v.y - __bfloat162float(h1));
    __nv_bfloat16 l2 = __float2bfloat16_rn(v.z - __bfloat162float(h2));
    __nv_bfloat16 l3 = __float2bfloat16_rn(v.w - __bfloat162float(h3));
    __nv_bfloat16* row = Y + m * (size_t)(3*K);
    __nv_bfloat162* p0 = (__nv_bfloat162*)(row + k4);
    __nv_bfloat162* p1 = (__nv_bfloat162*)(row + K + k4);
    __nv_bfloat162* p2 = (__nv_bfloat162*)(row + 2*K + k4);
    p0[0] = __halves2bfloat162(h0, h1); p0[1] = __halves2bfloat162(h2, h3);
    p1[0] = __halves2bfloat162(h0, h1); p1[1] = __halves2bfloat162(h2, h3);
    p2[0] = __halves2bfloat162(l0, l1); p2[1] = __halves2bfloat162(l2, l3);
}

// weights: W[K,N] f32 -> Y[N, 3K] bf16 transposed: [0:K]=hi, [K:2K]=lo, [2K:3K]=hi
__global__ void conv_wt(const float* __restrict__ W, __nv_bfloat16* __restrict__ Y,
                        int K, int N)
{
    __shared__ float t[32][33];
    int n0 = blockIdx.x * 32, k0 = blockIdx.y * 32;
    int tx = threadIdx.x, ty = threadIdx.y;
#pragma unroll
    for (int j = 0; j < 32; j += 8)
        t[ty+j][tx] = W[(size_t)(k0+ty+j) * N + n0 + tx];
    __syncthreads();
#pragma unroll
    for (int j = 0; j < 32; j += 8) {
        int n = n0 + ty + j, k = k0 + tx;
        float x = t[tx][ty+j];
        __nv_bfloat16 h = __float2bfloat16_rn(x);
        __nv_bfloat16 l = __float2bfloat16_rn(x - __bfloat162float(h));
        __nv_bfloat16* row = Y + (size_t)n * (3*K);
        row[k] = h; row[K + k] = l; row[2*K + k] = h;
    }
}

// ---------------------------------------------------------------------------
// fp32 register-tiled GEMM (projections only; small)
// ---------------------------------------------------------------------------
template<int BM,int BN,int BK,int TM,int TN,bool GATHER,bool BIAS>
__global__ void __launch_bounds__((BM/TM)*(BN/TN), 2)
gemm_k(const float* __restrict__ A, const float* __restrict__ Bw,
       const float* __restrict__ bias, float* __restrict__ C,
       int M, int N, int K,
       int rows_used, int rows_total, int row_off)
{
    constexpr int NT   = (BM/TM)*(BN/TN);
    constexpr int ASTR = BM + 4;
    constexpr int K4   = BK/4;
    constexpr int LA   = (BM*BK)/(4*NT);
    constexpr int LB   = (BK*BN)/(4*NT);

    __shared__ float As[BK*ASTR];
    __shared__ float Bs[BK*BN];

    const int t  = threadIdx.x;
    const int bm = blockIdx.y * BM;
    const int bn = blockIdx.x * BN;

    int  a_m[LA], a_k4[LA];
    long a_base[LA];
    bool a_ok[LA];
#pragma unroll
    for (int i = 0; i < LA; i++) {
        int f   = t + i*NT;
        a_m[i]  = f / K4;
        a_k4[i] = f % K4;
        int gr  = bm + a_m[i];
        a_ok[i] = (gr < M);
        int pr  = gr;
        if (GATHER) pr = (gr / rows_used) * rows_total + row_off + (gr % rows_used);
        a_base[i] = (long)(a_ok[i] ? pr : 0) * K;
    }
    int b_k[LB], b_n4[LB];
#pragma unroll
    for (int i = 0; i < LB; i++) {
        int f    = t + i*NT;
        b_k[i]   = f / (BN/4);
        b_n4[i]  = f % (BN/4);
    }

    const int rowg = (t / (BN/TN)) * TM;
    const int colg = (t % (BN/TN)) * TN;

    float acc[TM][TN];
#pragma unroll
    for (int i = 0; i < TM; i++)
#pragma unroll
        for (int j = 0; j < TN; j++) acc[i][j] = 0.f;

    const int nkt = K / BK;
    float4 ar[LA], br[LB];

    auto loadg = [&](int kt) {
#pragma unroll
        for (int i = 0; i < LA; i++) {
            if (a_ok[i])
                ar[i] = *(const float4*)(A + a_base[i] + (long)kt*BK + a_k4[i]*4);
            else
                ar[i] = make_float4(0.f, 0.f, 0.f, 0.f);
        }
#pragma unroll
        for (int i = 0; i < LB; i++)
            br[i] = *(const float4*)(Bw + (long)(kt*BK + b_k[i])*N + bn + b_n4[i]*4);
    };
    auto store_s = [&]() {
#pragma unroll
        for (int i = 0; i < LA; i++) {
            As[(a_k4[i]*4 + 0)*ASTR + a_m[i]] = ar[i].x;
            As[(a_k4[i]*4 + 1)*ASTR + a_m[i]] = ar[i].y;
            As[(a_k4[i]*4 + 2)*ASTR + a_m[i]] = ar[i].z;
            As[(a_k4[i]*4 + 3)*ASTR + a_m[i]] = ar[i].w;
        }
#pragma unroll
        for (int i = 0; i < LB; i++)
            *(float4*)(&Bs[b_k[i]*BN + b_n4[i]*4]) = br[i];
    };

    loadg(0);
    store_s();
    __syncthreads();

    for (int kt = 0; kt < nkt; kt++) {
        if (kt + 1 < nkt) loadg(kt + 1);
#pragma unroll
        for (int k = 0; k < BK; k++) {
            float a[TM], b[TN];
#pragma unroll
            for (int i = 0; i < TM; i++) a[i] = As[k*ASTR + rowg + i];
#pragma unroll
            for (int j = 0; j < TN; j++) b[j] = Bs[k*BN + colg + j];
#pragma unroll
            for (int i = 0; i < TM; i++)
#pragma unroll
                for (int j = 0; j < TN; j++)
                    acc[i][j] += a[i] * b[j];
        }
        __syncthreads();
        if (kt + 1 < nkt) { store_s(); __syncthreads(); }
    }

#pragma unroll
    for (int i = 0; i < TM; i++) {
        int gr = bm + rowg + i;
        if (gr >= M) continue;
#pragma unroll
        for (int j = 0; j < TN; j += 4) {
            int gc = bn + colg + j;
            float4 v;
            v.x = acc[i][j+0]; v.y = acc[i][j+1]; v.z = acc[i][j+2]; v.w = acc[i][j+3];
            if (BIAS) {
                v.x += bias[gc+0]; v.y += bias[gc+1];
                v.z += bias[gc+2]; v.w += bias[gc+3];
            }
            *(float4*)(C + (long)gr*N + gc) = v;
        }
    }
}

// ---------------------------------------------------------------------------
// Fused dual attention
// ---------------------------------------------------------------------------
#define CHQ      512
#define AT_WARPS 8
#define PS_STR   96

__global__ void __launch_bounds__(256, 2)
attn_k(const float* __restrict__ Q, const float* __restrict__ K,
       const float* __restrict__ V, const float* __restrict__ Kip,
       const float* __restrict__ Vip, float* __restrict__ O)
{
    extern __shared__ float sm[];
    float* Ks  = sm;
    float* Vs  = Ks  + NKEY*DP;
    float* Kis = Vs  + NKEY*DP;
    float* Vis = Kis + NIP*DP;
    float* Ps  = Vis + NIP*DP;
    float* Pip = Ps  + AT_WARPS*2*PS_STR;

    const int b    = blockIdx.z;
    const int h    = blockIdx.y;
    const int ch   = blockIdx.x;
    const int tid  = threadIdx.x;
    const int w    = tid >> 5;
    const int lane = tid & 31;

    for (int idx = tid; idx < NKEY*DH; idx += 256) {
        int s = idx / DH, d = idx % DH;
        long src = (long)(b*NKEY + s)*HS + h*DH + d;
        Ks[s*DP + d] = K[src];
        Vs[s*DP + d] = V[src];
    }
    for (int idx = tid; idx < NIP*DH; idx += 256) {
        int s = idx / DH, d = idx % DH;
        long src = (long)(b*NIP + s)*HS + h*DH + d;
        Kis[s*DP + d] = Kip[src];
        Vis[s*DP + d] = Vip[src];
    }
    __syncthreads();

    const float scale = 0.07905694150420949f;

    int  krow[3]; bool kval[3];
#pragma unroll
    for (int j = 0; j < 3; j++) {
        int s   = lane + 32*j;
        kval[j] = (s < NKEY);
        krow[j] = (kval[j] ? s : 0) * DP;
    }
    const int iprow = (lane < NIP ? lane : 0) * DP;

    for (int qp = w; qp < CHQ/2; qp += AT_WARPS) {
        const int  q0 = ch*CHQ + qp*2;
        const long r0 = ((long)b*SEQ + q0)*HS + h*DH;

        float qv0[5], qv1[5];
#pragma unroll
        for (int i = 0; i < 5; i++) {
            qv0[i] = Q[r0 +      lane + 32*i];
            qv1[i] = Q[r0 + HS + lane + 32*i];
        }

        float sc0[3] = {0.f,0.f,0.f}, sc1[3] = {0.f,0.f,0.f};
        float si0 = 0.f, si1 = 0.f;
#pragma unroll
        for (int i = 0; i < 5; i++) {
            float a0 = qv0[i], a1 = qv1[i];
#pragma unroll 8
            for (int dd = 0; dd < 32; dd++) {
                float qd0 = __shfl_sync(0xffffffffu, a0, dd);
                float qd1 = __shfl_sync(0xffffffffu, a1, dd);
                const float* kp = Ks + i*32 + dd;
                float k0 = kp[krow[0]], k1 = kp[krow[1]], k2 = kp[krow[2]];
                sc0[0] += qd0*k0; sc0[1] += qd0*k1; sc0[2] += qd0*k2;
                sc1[0] += qd1*k0; sc1[1] += qd1*k1; sc1[2] += qd1*k2;
                float kiv = Kis[iprow + i*32 + dd];
                si0 += qd0*kiv; si1 += qd1*kiv;
            }
        }

        float m0 = -1e30f, m1 = -1e30f;
#pragma unroll
        for (int j = 0; j < 3; j++) {
            sc0[j] = kval[j] ? sc0[j]*scale : -1e30f;
            sc1[j] = kval[j] ? sc1[j]*scale : -1e30f;
            m0 = fmaxf(m0, sc0[j]);
            m1 = fmaxf(m1, sc1[j]);
        }
#pragma unroll
        for (int off = 16; off >= 1; off >>= 1) {
            m0 = fmaxf(m0, __shfl_xor_sync(0xffffffffu, m0, off));
            m1 = fmaxf(m1, __shfl_xor_sync(0xffffffffu, m1, off));
        }
        float e0[3], e1[3], s0 = 0.f, s1 = 0.f;
#pragma unroll
        for (int j = 0; j < 3; j++) {
            e0[j] = __expf(sc0[j] - m0); s0 += e0[j];
            e1[j] = __expf(sc1[j] - m1); s1 += e1[j];
        }
#pragma unroll
        for (int off = 16; off >= 1; off >>= 1) {
            s0 += __shfl_xor_sync(0xffffffffu, s0, off);
            s1 += __shfl_xor_sync(0xffffffffu, s1, off);
        }
        const float inv0 = 1.f / s0, inv1 = 1.f / s1;

        __syncwarp();
        float* Prow0 = Ps + (w*2 + 0)*PS_STR;
        float* Prow1 = Ps + (w*2 + 1)*PS_STR;
#pragma unroll
        for (int j = 0; j < 3; j++) {
            Prow0[lane + 32*j] = e0[j] * inv0;
            Prow1[lane + 32*j] = e1[j] * inv1;
        }
        if (lane < NIP) {
            Pip[(w*2 + 0)*NIP + lane] = si0 * scale;
            Pip[(w*2 + 1)*NIP + lane] = si1 * scale;
        }
        __syncwarp();

        float pi0[NIP], pi1[NIP];
        {
            float mm0 = -1e30f, mm1 = -1e30f;
#pragma unroll
            for (int s = 0; s < NIP; s++) {
                pi0[s] = Pip[(w*2 + 0)*NIP + s]; mm0 = fmaxf(mm0, pi0[s]);
                pi1[s] = Pip[(w*2 + 1)*NIP + s]; mm1 = fmaxf(mm1, pi1[s]);
            }
            float ss0 = 0.f, ss1 = 0.f;
#pragma unroll
            for (int s = 0; s < NIP; s++) {
                pi0[s] = __expf(pi0[s] - mm0); ss0 += pi0[s];
                pi1[s] = __expf(pi1[s] - mm1); ss1 += pi1[s];
            }
            float is0 = 1.f/ss0, is1 = 1.f/ss1;
#pragma unroll
            for (int s = 0; s < NIP; s++) { pi0[s] *= is0; pi1[s] *= is1; }
        }

        float o0[5] = {0.f,0.f,0.f,0.f,0.f};
        float o1[5] = {0.f,0.f,0.f,0.f,0.f};
        for (int s = 0; s < NKEY; s++) {
            float p0 = Prow0[s], p1 = Prow1[s];
            const float* vp = Vs + s*DP + lane;
#pragma unroll
            for (int i = 0; i < 5; i++) {
                float v = vp[32*i];
                o0[i] += p0 * v;
                o1[i] += p1 * v;
            }
        }
#pragma unroll
        for (int s = 0; s < NIP; s++) {
            const float* vp = Vis + s*DP + lane;
#pragma unroll
            for (int i = 0; i < 5; i++) {
                float v = vp[32*i];
                o0[i] += pi0[s] * v;
                o1[i] += pi1[s] * v;
            }
        }
#pragma unroll
        for (int i = 0; i < 5; i++) {
            O[r0 +      lane + 32*i] = o0[i];
            O[r0 + HS + lane + 32*i] = o1[i];
        }
        __syncwarp();
    }
}

// ---------------------------------------------------------------------------
// Launch
// ---------------------------------------------------------------------------
static const int ATT_SMEM =
    (2*NKEY*DP + 2*NIP*DP + AT_WARPS*2*PS_STR + AT_WARPS*2*NIP) * (int)sizeof(float);

extern "C" void kernel_launch(void* const* d_in, const int* in_sizes, int n_in,
                              void* d_out, int out_size)
{
    const float* hs   = (const float*)d_in[0];
    const float* ehs  = (const float*)d_in[1];
    const float* w_q  = (const float*)d_in[2];
    const float* w_k  = (const float*)d_in[3];
    const float* w_v  = (const float*)d_in[4];
    const float* w_ki = (const float*)d_in[5];
    const float* w_vi = (const float*)d_in[6];
    const float* w_o  = (const float*)d_in[7];
    const float* b_o  = (const float*)d_in[8];
    float* out = (float*)d_out;

    float *Qb, *Kb, *Vb, *Kib, *Vib, *Ab;
    __nv_bfloat16 *Abf, *Wbf;
    cudaGetSymbolAddress((void**)&Qb,  g_Q);
    cudaGetSymbolAddress((void**)&Kb,  g_K);
    cudaGetSymbolAddress((void**)&Vb,  g_V);
    cudaGetSymbolAddress((void**)&Kib, g_Kip);
    cudaGetSymbolAddress((void**)&Vib, g_Vip);
    cudaGetSymbolAddress((void**)&Ab,  g_Attn);
    cudaGetSymbolAddress((void**)&Abf, g_Ab);
    cudaGetSymbolAddress((void**)&Wbf, g_Wb);

    cudaFuncSetAttribute(attn_k, cudaFuncAttributeMaxDynamicSharedMemorySize, ATT_SMEM);
    cudaFuncSetAttribute(mma_gemm<false>, cudaFuncAttributeMaxDynamicSharedMemorySize, MMA_SMEM);
    cudaFuncSetAttribute(mma_gemm<true>,  cudaFuncAttributeMaxDynamicSharedMemorySize, MMA_SMEM);

    const int CT = 256;
    const size_t totA = (size_t)MQ * (HS/4);
    dim3 gm(HS/128, MQ/128);   // (10, 256)

    // ---- Q = hidden @ w_q  (bf16-split HMMA) ----
    conv_act<<<(unsigned)((totA + CT-1)/CT), CT>>>(hs, Abf, MQ, HS);
    conv_wt<<<dim3(HS/32, HS/32), dim3(32, 8)>>>(w_q, Wbf, HS, HS);
    mma_gemm<false><<<gm, 256, MMA_SMEM>>>(Abf, Wbf, nullptr, Qb, HS);

    // ---- K/V projections (fp32, small) ----
    dim3 gkv(HS/64, (BATCH*NKEY + 63)/64);
    gemm_k<64,64,16,4,4,true,false><<<gkv, 256>>>(ehs, w_k, nullptr, Kb,
                                                  BATCH*NKEY, HS, CROSSD, NKEY, 81, 0);
    gemm_k<64,64,16,4,4,true,false><<<gkv, 256>>>(ehs, w_v, nullptr, Vb,
                                                  BATCH*NKEY, HS, CROSSD, NKEY, 81, 0);
    dim3 gip(HS/64, 1);
    gemm_k<64,64,16,4,4,true,false><<<gip, 256>>>(ehs, w_ki, nullptr, Kib,
                                                  BATCH*NIP, HS, CROSSD, NIP, 81, NKEY);
    gemm_k<64,64,16,4,4,true,false><<<gip, 256>>>(ehs, w_vi, nullptr, Vib,
                                                  BATCH*NIP, HS, CROSSD, NIP, 81, NKEY);

    // ---- fused dual attention ----
    dim3 ga(SEQ/CHQ, HEADS, BATCH);
    attn_k<<<ga, 256, ATT_SMEM>>>(Qb, Kb, Vb, Kib, Vib, Ab);

    // ---- out = attn @ w_out + b  (bf16-split HMMA) ----
    conv_act<<<(unsigned)((totA + CT-1)/CT), CT>>>(Ab, Abf, MQ, HS);
    conv_wt<<<dim3(HS/32, HS/32), dim3(32, 8)>>>(w_o, Wbf, HS, HS);
    mma_gemm<true><<<gm, 256, MMA_SMEM>>>(Abf, Wbf, b_o, out, HS);
}

// round 8
// speedup vs baseline: 2.1387x; 1.2025x over previous
#include <cuda.h>
#include <cuda_runtime.h>
#include <cuda_bf16.h>
#include <math.h>
#include <stdint.h>

// ---------------------------------------------------------------------------
// Problem constants
// ---------------------------------------------------------------------------
#define BATCH   8
#define SEQ     4096
#define HS      1280
#define HEADS   8
#define DH      160
#define DP      161
#define NKEY    77
#define NIP     4
#define CROSSD  2048
#define MQ      (BATCH*SEQ)      // 32768
#define KP      (2*HS)           // 2560  ([hi | lo] packed K)

// Scratch device globals (allocation-free workaround)
__device__ float g_Q[MQ * HS];
__device__ float g_Attn[MQ * HS];
__device__ float g_K[BATCH * NKEY * HS];
__device__ float g_V[BATCH * NKEY * HS];
__device__ float g_Kip[BATCH * NIP * HS];
__device__ float g_Vip[BATCH * NIP * HS];
__device__ __nv_bfloat16 g_Ab[(size_t)MQ * KP];   // packed activations [hi|lo]
__device__ __nv_bfloat16 g_Wb[(size_t)HS * KP];   // packed weight^T    [hi|lo]

// ---------------------------------------------------------------------------
// Portable tensor-core GEMM (mma.sync bf16, cp.async, ldmatrix — sm_80+ ISA)
// C[M,N](f32) = (Ahi+Alo)[M,K] @ (Bhi+Blo)[N,K]^T   (3-term, lo*lo dropped)
// CTA tile 128x128, K chunk 64 (128B SW128-swizzled rows), 3-stage pipeline.
// Per chunk: 4 tiles (Ahi, Alo, Bhi, Blo); MMA terms issued from registers.
// ---------------------------------------------------------------------------
#define ST    3
#define KC    64
#define NCH   (HS/KC)              // 20
#define TSTG  16384                // one 128x64 bf16 tile
#define STG4  (4*TSTG)             // 65536 per stage
#define MMA_SMEM (1024 + ST*STG4)  // 197632

__device__ __forceinline__ uint32_t smem_u32(const void* p) {
    uint32_t a;
    asm("{ .reg .u64 t; cvta.to.shared.u64 t, %1; cvt.u32.u64 %0, t; }"
        : "=r"(a) : "l"(p));
    return a;
}

#define CP_ASYNC16(dst, src) \
    asm volatile("cp.async.cg.shared.global [%0], [%1], 16;" \
        :: "r"(dst), "l"(src) : "memory")
#define CP_COMMIT() asm volatile("cp.async.commit_group;" ::: "memory")
#define CP_WAIT(n)  asm volatile("cp.async.wait_group %0;" :: "n"(n) : "memory")

#define LDSM4(r, addr) \
    asm volatile("ldmatrix.sync.aligned.m8n8.x4.shared.b16 {%0,%1,%2,%3}, [%4];" \
        : "=r"((r)[0]), "=r"((r)[1]), "=r"((r)[2]), "=r"((r)[3]) : "r"(addr))

#define MMA16816(d, a, b0, b1) \
    asm volatile("mma.sync.aligned.m16n8k16.row.col.f32.bf16.bf16.f32 " \
        "{%0,%1,%2,%3}, {%4,%5,%6,%7}, {%8,%9}, {%0,%1,%2,%3};" \
        : "+f"((d)[0]), "+f"((d)[1]), "+f"((d)[2]), "+f"((d)[3]) \
        : "r"((a)[0]), "r"((a)[1]), "r"((a)[2]), "r"((a)[3]), "r"(b0), "r"(b1))

template<bool BIAS>
__global__ void __launch_bounds__(256, 1)
mma_gemm(const __nv_bfloat16* __restrict__ Ag, const __nv_bfloat16* __restrict__ Bg,
         const float* __restrict__ bias, float* __restrict__ C, int N)
{
    extern __shared__ char dsm[];
    const uint32_t sb = (smem_u32(dsm) + 1023u) & ~1023u;
    const int tid  = threadIdx.x;
    const int lane = tid & 31;
    const int wid  = tid >> 5;
    const int wm   = wid >> 2;        // 0..1  (64-row slab)
    const int wn   = wid & 3;         // 0..3  (32-col slab)
    const int mt   = blockIdx.y, nt = blockIdx.x;

    const __nv_bfloat16* Abase = Ag + (size_t)(mt*128) * KP;
    const __nv_bfloat16* Bbase = Bg + (size_t)(nt*128) * KP;

    // cp.async loader: per tile, 4 x 16B per thread (1024 chunks / 256 thr)
    int ld_row[4], ld_sw[4], ld_c8[4];
#pragma unroll
    for (int i = 0; i < 4; i++) {
        int idx   = tid + i*256;
        ld_row[i] = idx >> 3;
        int c     = idx & 7;
        ld_c8[i]  = c * 8;
        ld_sw[i]  = (c ^ (ld_row[i] & 7)) << 4;
    }

    auto load_chunk = [&](int ck, int st) {
        const uint32_t s0 = sb + st*STG4;
        const __nv_bfloat16* src[4] = {
            Abase + ck*KC,          // Ahi
            Abase + HS + ck*KC,     // Alo
            Bbase + ck*KC,          // Bhi
            Bbase + HS + ck*KC      // Blo
        };
#pragma unroll
        for (int tld = 0; tld < 4; tld++) {
            const uint32_t ts = s0 + tld*TSTG;
            const __nv_bfloat16* g = src[tld];
#pragma unroll
            for (int i = 0; i < 4; i++)
                CP_ASYNC16(ts + ld_row[i]*128 + ld_sw[i],
                           g + (size_t)ld_row[i]*KP + ld_c8[i]);
        }
    };

    float acc[4][4][4];
#pragma unroll
    for (int mi = 0; mi < 4; mi++)
#pragma unroll
        for (int ni = 0; ni < 4; ni++)
#pragma unroll
            for (int j = 0; j < 4; j++) acc[mi][ni][j] = 0.f;

    // ldmatrix lane addressing
    const int a_row  = wm*64 + (lane & 15);                        // + mi*16
    const int b_row  = wn*32 + ((lane >> 3) >> 1)*8 + (lane & 7);  // + p*16
    const int a_coff = lane >> 4;
    const int b_coff = (lane >> 3) & 1;

    // prologue
    load_chunk(0, 0); CP_COMMIT();
    load_chunk(1, 1); CP_COMMIT();

    int st = 0, pst = 2;
    for (int ck = 0; ck < NCH; ck++) {
        CP_WAIT(1);
        __syncthreads();

        if (ck + 2 < NCH) load_chunk(ck + 2, pst);
        CP_COMMIT();

        const uint32_t ah_s = sb + st*STG4;
        const uint32_t al_s = ah_s + TSTG;
        const uint32_t bh_s = ah_s + 2*TSTG;
        const uint32_t bl_s = ah_s + 3*TSTG;

#pragma unroll
        for (int ks = 0; ks < 4; ks++) {
            uint32_t ah[4][4], al[4][4], bh[2][4], bl[2][4];
#pragma unroll
            for (int mi = 0; mi < 4; mi++) {
                int row = a_row + mi*16;
                int c   = ks*2 + a_coff;
                uint32_t off = row*128 + ((c ^ (row & 7)) << 4);
                LDSM4(ah[mi], ah_s + off);
                LDSM4(al[mi], al_s + off);
            }
#pragma unroll
            for (int p = 0; p < 2; p++) {
                int row = b_row + p*16;
                int c   = ks*2 + b_coff;
                uint32_t off = row*128 + ((c ^ (row & 7)) << 4);
                LDSM4(bh[p], bh_s + off);
                LDSM4(bl[p], bl_s + off);
            }
#pragma unroll
            for (int mi = 0; mi < 4; mi++)
#pragma unroll
                for (int ni = 0; ni < 4; ni++) {
                    const int q = ni >> 1, r = (ni & 1)*2;
                    MMA16816(acc[mi][ni], ah[mi], bh[q][r], bh[q][r+1]);
                    MMA16816(acc[mi][ni], ah[mi], bl[q][r], bl[q][r+1]);
                    MMA16816(acc[mi][ni], al[mi], bh[q][r], bh[q][r+1]);
                }
        }
        __syncthreads();
        st  = (st  + 1 == ST) ? 0 : st  + 1;
        pst = (pst + 1 == ST) ? 0 : pst + 1;
    }

    // epilogue: registers -> gmem fp32
    const int g = lane >> 2, tq = lane & 3;
#pragma unroll
    for (int mi = 0; mi < 4; mi++) {
#pragma unroll
        for (int ni = 0; ni < 4; ni++) {
            int row0 = mt*128 + wm*64 + mi*16 + g;
            int col  = nt*128 + wn*32 + ni*8 + tq*2;
            float bx = 0.f, by = 0.f;
            if (BIAS) { bx = bias[col]; by = bias[col+1]; }
            float2 v0 = { acc[mi][ni][0] + bx, acc[mi][ni][1] + by };
            float2 v1 = { acc[mi][ni][2] + bx, acc[mi][ni][3] + by };
            *(float2*)(C + (size_t)row0 * N + col)     = v0;
            *(float2*)(C + (size_t)(row0+8) * N + col) = v1;
        }
    }
}

// ---------------------------------------------------------------------------
// fp32 -> packed bf16 split conversions.  Row layout: [0:K]=hi, [K:2K]=lo
// ---------------------------------------------------------------------------
__global__ void conv_act(const float* __restrict__ X, __nv_bfloat16* __restrict__ Y,
                         int M, int K)
{
    size_t i = (size_t)blockIdx.x * blockDim.x + threadIdx.x;
    size_t tot = (size_t)M * (K/4);
    if (i >= tot) return;
    size_t m = i / (K/4); int k4 = (int)(i % (K/4)) * 4;
    float4 v = reinterpret_cast<const float4*>(X)[i];
    __nv_bfloat16 h0 = __float2bfloat16_rn(v.x), h1 = __float2bfloat16_rn(v.y);
    __nv_bfloat16 h2 = __float2bfloat16_rn(v.z), h3 = __float2bfloat16_rn(v.w);
    __nv_bfloat16 l0 = __float2bfloat16_rn(v.x - __bfloat162float(h0));
    __nv_bfloat16 l1 = __float2bfloat16_rn(v.y - __bfloat162float(h1));
    __nv_bfloat16 l2 = __float2bfloat16_rn(v.z - __bfloat162float(h2));
    __nv_bfloat16 l3 = __float2bfloat16_rn(v.w - __bfloat162float(h3));
    __nv_bfloat16* row = Y + m * (size_t)(2*K);
    __nv_bfloat162* p0 = (__nv_bfloat162*)(row + k4);
    __nv_bfloat162* p1 = (__nv_bfloat162*)(row + K + k4);
    p0[0] = __halves2bfloat162(h0, h1); p0[1] = __halves2bfloat162(h2, h3);
    p1[0] = __halves2bfloat162(l0, l1); p1[1] = __halves2bfloat162(l2, l3);
}

// weights: W[K,N] f32 -> Y[N, 2K] bf16 transposed: [0:K]=hi, [K:2K]=lo
__global__ void conv_wt(const float* __restrict__ W, __nv_bfloat16* __restrict__ Y,
                        int K, int N)
{
    __shared__ float t[32][33];
    int n0 = blockIdx.x * 32, k0 = blockIdx.y * 32;
    int tx = threadIdx.x, ty = threadIdx.y;
#pragma unroll
    for (int j = 0; j < 32; j += 8)
        t[ty+j][tx] = W[(size_t)(k0+ty+j) * N + n0 + tx];
    __syncthreads();
#pragma unroll
    for (int j = 0; j < 32; j += 8) {
        int n = n0 + ty + j, k = k0 + tx;
        float x = t[tx][ty+j];
        __nv_bfloat16 h = __float2bfloat16_rn(x);
        __nv_bfloat16 l = __float2bfloat16_rn(x - __bfloat162float(h));
        __nv_bfloat16* row = Y + (size_t)n * (2*K);
        row[k] = h; row[K + k] = l;
    }
}

// ---------------------------------------------------------------------------
// fp32 register-tiled GEMM with dual weight/output (merged projections).
// Logical N = 2*Nh; columns [0,Nh) use B1->C1, [Nh,2Nh) use B2->C2.
// BN must divide Nh.
// ---------------------------------------------------------------------------
template<int BM,int BN,int BK,int TM,int TN,bool GATHER>
__global__ void __launch_bounds__((BM/TM)*(BN/TN), 2)
gemm2_k(const float* __restrict__ A,
        const float* __restrict__ B1, const float* __restrict__ B2,
        float* __restrict__ C1, float* __restrict__ C2,
        int M, int Nh, int K,
        int rows_used, int rows_total, int row_off)
{
    constexpr int NT   = (BM/TM)*(BN/TN);
    constexpr int ASTR = BM + 4;
    constexpr int K4   = BK/4;
    constexpr int LA   = (BM*BK)/(4*NT);
    constexpr int LB   = (BK*BN)/(4*NT);

    __shared__ float As[BK*ASTR];
    __shared__ float Bs[BK*BN];

    const int t   = threadIdx.x;
    const int bm  = blockIdx.y * BM;
    int bnL       = blockIdx.x * BN;
    const float* Bw = (bnL < Nh) ? B1 : B2;
    float*       C  = (bnL < Nh) ? C1 : C2;
    const int bn  = (bnL < Nh) ? bnL : bnL - Nh;
    const int N   = Nh;

    int  a_m[LA], a_k4[LA];
    long a_base[LA];
    bool a_ok[LA];
#pragma unroll
    for (int i = 0; i < LA; i++) {
        int f   = t + i*NT;
        a_m[i]  = f / K4;
        a_k4[i] = f % K4;
        int gr  = bm + a_m[i];
        a_ok[i] = (gr < M);
        int pr  = gr;
        if (GATHER) pr = (gr / rows_used) * rows_total + row_off + (gr % rows_used);
        a_base[i] = (long)(a_ok[i] ? pr : 0) * K;
    }
    int b_k[LB], b_n4[LB];
#pragma unroll
    for (int i = 0; i < LB; i++) {
        int f    = t + i*NT;
        b_k[i]   = f / (BN/4);
        b_n4[i]  = f % (BN/4);
    }

    const int rowg = (t / (BN/TN)) * TM;
    const int colg = (t % (BN/TN)) * TN;

    float acc[TM][TN];
#pragma unroll
    for (int i = 0; i < TM; i++)
#pragma unroll
        for (int j = 0; j < TN; j++) acc[i][j] = 0.f;

    const int nkt = K / BK;
    float4 ar[LA], br[LB];

    auto loadg = [&](int kt) {
#pragma unroll
        for (int i = 0; i < LA; i++) {
            if (a_ok[i])
                ar[i] = *(const float4*)(A + a_base[i] + (long)kt*BK + a_k4[i]*4);
            else
                ar[i] = make_float4(0.f, 0.f, 0.f, 0.f);
        }
#pragma unroll
        for (int i = 0; i < LB; i++)
            br[i] = *(const float4*)(Bw + (long)(kt*BK + b_k[i])*N + bn + b_n4[i]*4);
    };
    auto store_s = [&]() {
#pragma unroll
        for (int i = 0; i < LA; i++) {
            As[(a_k4[i]*4 + 0)*ASTR + a_m[i]] = ar[i].x;
            As[(a_k4[i]*4 + 1)*ASTR + a_m[i]] = ar[i].y;
            As[(a_k4[i]*4 + 2)*ASTR + a_m[i]] = ar[i].z;
            As[(a_k4[i]*4 + 3)*ASTR + a_m[i]] = ar[i].w;
        }
#pragma unroll
        for (int i = 0; i < LB; i++)
            *(float4*)(&Bs[b_k[i]*BN + b_n4[i]*4]) = br[i];
    };

    loadg(0);
    store_s();
    __syncthreads();

    for (int kt = 0; kt < nkt; kt++) {
        if (kt + 1 < nkt) loadg(kt + 1);
#pragma unroll
        for (int k = 0; k < BK; k++) {
            float a[TM], b[TN];
#pragma unroll
            for (int i = 0; i < TM; i++) a[i] = As[k*ASTR + rowg + i];
#pragma unroll
            for (int j = 0; j < TN; j++) b[j] = Bs[k*BN + colg + j];
#pragma unroll
            for (int i = 0; i < TM; i++)
#pragma unroll
                for (int j = 0; j < TN; j++)
                    acc[i][j] += a[i] * b[j];
        }
        __syncthreads();
        if (kt + 1 < nkt) { store_s(); __syncthreads(); }
    }

#pragma unroll
    for (int i = 0; i < TM; i++) {
        int gr = bm + rowg + i;
        if (gr >= M) continue;
#pragma unroll
        for (int j = 0; j < TN; j += 4) {
            int gc = bn + colg + j;
            float4 v;
            v.x = acc[i][j+0]; v.y = acc[i][j+1]; v.z = acc[i][j+2]; v.w = acc[i][j+3];
            *(float4*)(C + (long)gr*N + gc) = v;
        }
    }
}

// ---------------------------------------------------------------------------
// Fused dual attention
// ---------------------------------------------------------------------------
#define CHQ      512
#define AT_WARPS 8
#define PS_STR   96

__global__ void __launch_bounds__(256, 2)
attn_k(const float* __restrict__ Q, const float* __restrict__ K,
       const float* __restrict__ V, const float* __restrict__ Kip,
       const float* __restrict__ Vip, float* __restrict__ O)
{
    extern __shared__ float sm[];
    float* Ks  = sm;
    float* Vs  = Ks  + NKEY*DP;
    float* Kis = Vs  + NKEY*DP;
    float* Vis = Kis + NIP*DP;
    float* Ps  = Vis + NIP*DP;
    float* Pip = Ps  + AT_WARPS*2*PS_STR;

    const int b    = blockIdx.z;
    const int h    = blockIdx.y;
    const int ch   = blockIdx.x;
    const int tid  = threadIdx.x;
    const int w    = tid >> 5;
    const int lane = tid & 31;

    for (int idx = tid; idx < NKEY*DH; idx += 256) {
        int s = idx / DH, d = idx % DH;
        long src = (long)(b*NKEY + s)*HS + h*DH + d;
        Ks[s*DP + d] = K[src];
        Vs[s*DP + d] = V[src];
    }
    for (int idx = tid; idx < NIP*DH; idx += 256) {
        int s = idx / DH, d = idx % DH;
        long src = (long)(b*NIP + s)*HS + h*DH + d;
        Kis[s*DP + d] = Kip[src];
        Vis[s*DP + d] = Vip[src];
    }
    __syncthreads();

    const float scale = 0.07905694150420949f;

    int  krow[3]; bool kval[3];
#pragma unroll
    for (int j = 0; j < 3; j++) {
        int s   = lane + 32*j;
        kval[j] = (s < NKEY);
        krow[j] = (kval[j] ? s : 0) * DP;
    }
    const int iprow = (lane < NIP ? lane : 0) * DP;

    for (int qp = w; qp < CHQ/2; qp += AT_WARPS) {
        const int  q0 = ch*CHQ + qp*2;
        const long r0 = ((long)b*SEQ + q0)*HS + h*DH;

        float qv0[5], qv1[5];
#pragma unroll
        for (int i = 0; i < 5; i++) {
            qv0[i] = Q[r0 +      lane + 32*i];
            qv1[i] = Q[r0 + HS + lane + 32*i];
        }

        float sc0[3] = {0.f,0.f,0.f}, sc1[3] = {0.f,0.f,0.f};
        float si0 = 0.f, si1 = 0.f;
#pragma unroll
        for (int i = 0; i < 5; i++) {
            float a0 = qv0[i], a1 = qv1[i];
#pragma unroll 8
            for (int dd = 0; dd < 32; dd++) {
                float qd0 = __shfl_sync(0xffffffffu, a0, dd);
                float qd1 = __shfl_sync(0xffffffffu, a1, dd);
                const float* kp = Ks + i*32 + dd;
                float k0 = kp[krow[0]], k1 = kp[krow[1]], k2 = kp[krow[2]];
                sc0[0] += qd0*k0; sc0[1] += qd0*k1; sc0[2] += qd0*k2;
                sc1[0] += qd1*k0; sc1[1] += qd1*k1; sc1[2] += qd1*k2;
                float kiv = Kis[iprow + i*32 + dd];
                si0 += qd0*kiv; si1 += qd1*kiv;
            }
        }

        float m0 = -1e30f, m1 = -1e30f;
#pragma unroll
        for (int j = 0; j < 3; j++) {
            sc0[j] = kval[j] ? sc0[j]*scale : -1e30f;
            sc1[j] = kval[j] ? sc1[j]*scale : -1e30f;
            m0 = fmaxf(m0, sc0[j]);
            m1 = fmaxf(m1, sc1[j]);
        }
#pragma unroll
        for (int off = 16; off >= 1; off >>= 1) {
            m0 = fmaxf(m0, __shfl_xor_sync(0xffffffffu, m0, off));
            m1 = fmaxf(m1, __shfl_xor_sync(0xffffffffu, m1, off));
        }
        float e0[3], e1[3], s0 = 0.f, s1 = 0.f;
#pragma unroll
        for (int j = 0; j < 3; j++) {
            e0[j] = __expf(sc0[j] - m0); s0 += e0[j];
            e1[j] = __expf(sc1[j] - m1); s1 += e1[j];
        }
#pragma unroll
        for (int off = 16; off >= 1; off >>= 1) {
            s0 += __shfl_xor_sync(0xffffffffu, s0, off);
            s1 += __shfl_xor_sync(0xffffffffu, s1, off);
        }
        const float inv0 = 1.f / s0, inv1 = 1.f / s1;

        __syncwarp();
        float* Prow0 = Ps + (w*2 + 0)*PS_STR;
        float* Prow1 = Ps + (w*2 + 1)*PS_STR;
#pragma unroll
        for (int j = 0; j < 3; j++) {
            Prow0[lane + 32*j] = e0[j] * inv0;
            Prow1[lane + 32*j] = e1[j] * inv1;
        }
        if (lane < NIP) {
            Pip[(w*2 + 0)*NIP + lane] = si0 * scale;
            Pip[(w*2 + 1)*NIP + lane] = si1 * scale;
        }
        __syncwarp();

        float pi0[NIP], pi1[NIP];
        {
            float mm0 = -1e30f, mm1 = -1e30f;
#pragma unroll
            for (int s = 0; s < NIP; s++) {
                pi0[s] = Pip[(w*2 + 0)*NIP + s]; mm0 = fmaxf(mm0, pi0[s]);
                pi1[s] = Pip[(w*2 + 1)*NIP + s]; mm1 = fmaxf(mm1, pi1[s]);
            }
            float ss0 = 0.f, ss1 = 0.f;
#pragma unroll
            for (int s = 0; s < NIP; s++) {
                pi0[s] = __expf(pi0[s] - mm0); ss0 += pi0[s];
                pi1[s] = __expf(pi1[s] - mm1); ss1 += pi1[s];
            }
            float is0 = 1.f/ss0, is1 = 1.f/ss1;
#pragma unroll
            for (int s = 0; s < NIP; s++) { pi0[s] *= is0; pi1[s] *= is1; }
        }

        float o0[5] = {0.f,0.f,0.f,0.f,0.f};
        float o1[5] = {0.f,0.f,0.f,0.f,0.f};
        for (int s = 0; s < NKEY; s++) {
            float p0 = Prow0[s], p1 = Prow1[s];
            const float* vp = Vs + s*DP + lane;
#pragma unroll
            for (int i = 0; i < 5; i++) {
                float v = vp[32*i];
                o0[i] += p0 * v;
                o1[i] += p1 * v;
            }
        }
#pragma unroll
        for (int s = 0; s < NIP; s++) {
            const float* vp = Vis + s*DP + lane;
#pragma unroll
            for (int i = 0; i < 5; i++) {
                float v = vp[32*i];
                o0[i] += pi0[s] * v;
                o1[i] += pi1[s] * v;
            }
        }
#pragma unroll
        for (int i = 0; i < 5; i++) {
            O[r0 +      lane + 32*i] = o0[i];
            O[r0 + HS + lane + 32*i] = o1[i];
        }
        __syncwarp();
    }
}

// ---------------------------------------------------------------------------
// Launch
// ---------------------------------------------------------------------------
static const int ATT_SMEM =
    (2*NKEY*DP + 2*NIP*DP + AT_WARPS*2*PS_STR + AT_WARPS*2*NIP) * (int)sizeof(float);

extern "C" void kernel_launch(void* const* d_in, const int* in_sizes, int n_in,
                              void* d_out, int out_size)
{
    const float* hs   = (const float*)d_in[0];
    const float* ehs  = (const float*)d_in[1];
    const float* w_q  = (const float*)d_in[2];
    const float* w_k  = (const float*)d_in[3];
    const float* w_v  = (const float*)d_in[4];
    const float* w_ki = (const float*)d_in[5];
    const float* w_vi = (const float*)d_in[6];
    const float* w_o  = (const float*)d_in[7];
    const float* b_o  = (const float*)d_in[8];
    float* out = (float*)d_out;

    float *Qb, *Kb, *Vb, *Kib, *Vib, *Ab;
    __nv_bfloat16 *Abf, *Wbf;
    cudaGetSymbolAddress((void**)&Qb,  g_Q);
    cudaGetSymbolAddress((void**)&Kb,  g_K);
    cudaGetSymbolAddress((void**)&Vb,  g_V);
    cudaGetSymbolAddress((void**)&Kib, g_Kip);
    cudaGetSymbolAddress((void**)&Vib, g_Vip);
    cudaGetSymbolAddress((void**)&Ab,  g_Attn);
    cudaGetSymbolAddress((void**)&Abf, g_Ab);
    cudaGetSymbolAddress((void**)&Wbf, g_Wb);

    cudaFuncSetAttribute(attn_k, cudaFuncAttributeMaxDynamicSharedMemorySize, ATT_SMEM);
    cudaFuncSetAttribute(mma_gemm<false>, cudaFuncAttributeMaxDynamicSharedMemorySize, MMA_SMEM);
    cudaFuncSetAttribute(mma_gemm<true>,  cudaFuncAttributeMaxDynamicSharedMemorySize, MMA_SMEM);

    const int CT = 256;
    const size_t totA = (size_t)MQ * (HS/4);
    dim3 gm(HS/128, MQ/128);   // (10, 256)

    // ---- Q = hidden @ w_q  (bf16-split HMMA) ----
    conv_act<<<(unsigned)((totA + CT-1)/CT), CT>>>(hs, Abf, MQ, HS);
    conv_wt<<<dim3(HS/32, HS/32), dim3(32, 8)>>>(w_q, Wbf, HS, HS);
    mma_gemm<false><<<gm, 256, MMA_SMEM>>>(Abf, Wbf, nullptr, Qb, HS);

    // ---- merged K|V and Kip|Vip projections (fp32, dual-B) ----
    dim3 gkv(2*HS/64, (BATCH*NKEY + 63)/64);   // (40, 10)
    gemm2_k<64,64,16,4,4,true><<<gkv, 256>>>(ehs, w_k, w_v, Kb, Vb,
                                             BATCH*NKEY, HS, CROSSD, NKEY, 81, 0);
    dim3 gip(2*HS/64, 1);                      // (40, 1)
    gemm2_k<64,64,16,4,4,true><<<gip, 256>>>(ehs, w_ki, w_vi, Kib, Vib,
                                             BATCH*NIP, HS, CROSSD, NIP, 81, NKEY);

    // ---- fused dual attention ----
    dim3 ga(SEQ/CHQ, HEADS, BATCH);
    attn_k<<<ga, 256, ATT_SMEM>>>(Qb, Kb, Vb, Kib, Vib, Ab);

    // ---- out = attn @ w_out + b  (bf16-split HMMA) ----
    conv_act<<<(unsigned)((totA + CT-1)/CT), CT>>>(Ab, Abf, MQ, HS);
    conv_wt<<<dim3(HS/32, HS/32), dim3(32, 8)>>>(w_o, Wbf, HS, HS);
    mma_gemm<true><<<gm, 256, MMA_SMEM>>>(Abf, Wbf, b_o, out, HS);
}

// round 10
// speedup vs baseline: 2.3423x; 1.0952x over previous
#include <cuda.h>
#include <cuda_runtime.h>
#include <cuda_bf16.h>
#include <math.h>
#include <stdint.h>

// ---------------------------------------------------------------------------
// Problem constants
// ---------------------------------------------------------------------------
#define BATCH   8
#define SEQ     4096
#define HS      1280
#define HEADS   8
#define DH      160
#define DP      161
#define NKEY    77
#define NIP     4
#define NCTX    81               // 77 text + 4 ip rows per batch
#define CROSSD  2048
#define MQ      (BATCH*SEQ)      // 32768
#define KP      (2*HS)           // 2560  ([hi|lo] packed K, K=1280)
#define KPE     (2*CROSSD)       // 4096  ([hi|lo] packed K, K=2048)
#define NQ      (4*HS)           // 5120  quad projection output columns
#define MEPAD   768              // 648 ctx rows padded to 6 CTA tiles

// Scratch device globals (allocation-free workaround)
__device__ float g_Q[MQ * HS];                     // Q projection (f32)
__device__ float g_KVq[MEPAD * NQ];                // quad proj out [K|V|Kip|Vip]
__device__ __nv_bfloat16 g_Ab[(size_t)MQ * KP];    // packed activations [hi|lo]
__device__ __nv_bfloat16 g_Wb[(size_t)HS * KP];    // packed weight^T [hi|lo] (1280x2560)
__device__ __nv_bfloat16 g_Eb[(size_t)MEPAD * KPE];// packed ehs [hi|lo] (768x4096)
__device__ __nv_bfloat16 g_Wq[(size_t)NQ * KPE];   // packed quad weight^T (5120x4096)

// ---------------------------------------------------------------------------
// PTX helpers (portable sm_80+ ISA only)
// ---------------------------------------------------------------------------
__device__ __forceinline__ uint32_t smem_u32(const void* p) {
    uint32_t a;
    asm("{ .reg .u64 t; cvta.to.shared.u64 t, %1; cvt.u32.u64 %0, t; }"
        : "=r"(a) : "l"(p));
    return a;
}

#define CP_ASYNC16(dst, src) \
    asm volatile("cp.async.cg.shared.global [%0], [%1], 16;" \
        :: "r"(dst), "l"(src) : "memory")
#define CP_COMMIT() asm volatile("cp.async.commit_group;" ::: "memory")
#define CP_WAIT(n)  asm volatile("cp.async.wait_group %0;" :: "n"(n) : "memory")

#define LDSM4(r, addr) \
    asm volatile("ldmatrix.sync.aligned.m8n8.x4.shared.b16 {%0,%1,%2,%3}, [%4];" \
        : "=r"((r)[0]), "=r"((r)[1]), "=r"((r)[2]), "=r"((r)[3]) : "r"(addr))

#define MMA16816(d, a, b0, b1) \
    asm volatile("mma.sync.aligned.m16n8k16.row.col.f32.bf16.bf16.f32 " \
        "{%0,%1,%2,%3}, {%4,%5,%6,%7}, {%8,%9}, {%0,%1,%2,%3};" \
        : "+f"((d)[0]), "+f"((d)[1]), "+f"((d)[2]), "+f"((d)[3]) \
        : "r"((a)[0]), "r"((a)[1]), "r"((a)[2]), "r"((a)[3]), "r"(b0), "r"(b1))

// ---------------------------------------------------------------------------
// Tensor-core GEMM (mma.sync bf16, cp.async, ldmatrix)
// C[M,N](f32) = (Ahi+Alo)[M,KD] @ (Bhi+Blo)[N,KD]^T   (3-term, lo*lo dropped)
// A/B rows packed as [hi(0:KD) | lo(KD:2KD)], row stride 2*KD.
// CTA tile 128x128, K chunk 64 (128B SW128-swizzled rows), 3-stage pipeline.
// ---------------------------------------------------------------------------
#define ST    3
#define KC    64
#define TSTG  16384                // one 128x64 bf16 tile
#define STG4  (4*TSTG)             // 65536 per stage (Ahi, Alo, Bhi, Blo)
#define MMA_SMEM (1024 + ST*STG4)  // 197632

template<int KD, bool BIAS>
__global__ void __launch_bounds__(256, 1)
mma_gemm(const __nv_bfloat16* __restrict__ Ag, const __nv_bfloat16* __restrict__ Bg,
         const float* __restrict__ bias, float* __restrict__ C, int N)
{
    constexpr int KPs = 2*KD;
    constexpr int NCH = KD/KC;
    extern __shared__ char dsm[];
    const uint32_t sb = (smem_u32(dsm) + 1023u) & ~1023u;
    const int tid  = threadIdx.x;
    const int lane = tid & 31;
    const int wid  = tid >> 5;
    const int wm   = wid >> 2;        // 0..1  (64-row slab)
    const int wn   = wid & 3;         // 0..3  (32-col slab)
    const int mt   = blockIdx.y, nt = blockIdx.x;

    const __nv_bfloat16* Abase = Ag + (size_t)(mt*128) * KPs;
    const __nv_bfloat16* Bbase = Bg + (size_t)(nt*128) * KPs;

    // cp.async loader: per tile, 4 x 16B per thread (1024 chunks / 256 thr)
    int ld_row[4], ld_sw[4], ld_c8[4];
#pragma unroll
    for (int i = 0; i < 4; i++) {
        int idx   = tid + i*256;
        ld_row[i] = idx >> 3;
        int c     = idx & 7;
        ld_c8[i]  = c * 8;
        ld_sw[i]  = (c ^ (ld_row[i] & 7)) << 4;
    }

    auto load_chunk = [&](int ck, int st) {
        const uint32_t s0 = sb + st*STG4;
        const __nv_bfloat16* src[4] = {
            Abase + ck*KC,          // Ahi
            Abase + KD + ck*KC,     // Alo
            Bbase + ck*KC,          // Bhi
            Bbase + KD + ck*KC      // Blo
        };
#pragma unroll
        for (int tld = 0; tld < 4; tld++) {
            const uint32_t ts = s0 + tld*TSTG;
            const __nv_bfloat16* g = src[tld];
#pragma unroll
            for (int i = 0; i < 4; i++)
                CP_ASYNC16(ts + ld_row[i]*128 + ld_sw[i],
                           g + (size_t)ld_row[i]*KPs + ld_c8[i]);
        }
    };

    float acc[4][4][4];
#pragma unroll
    for (int mi = 0; mi < 4; mi++)
#pragma unroll
        for (int ni = 0; ni < 4; ni++)
#pragma unroll
            for (int j = 0; j < 4; j++) acc[mi][ni][j] = 0.f;

    // ldmatrix lane addressing
    const int a_row  = wm*64 + (lane & 15);                        // + mi*16
    const int b_row  = wn*32 + ((lane >> 3) >> 1)*8 + (lane & 7);  // + p*16
    const int a_coff = lane >> 4;
    const int b_coff = (lane >> 3) & 1;

    // prologue
    load_chunk(0, 0); CP_COMMIT();
    load_chunk(1, 1); CP_COMMIT();

    int st = 0, pst = 2;
    for (int ck = 0; ck < NCH; ck++) {
        CP_WAIT(1);
        __syncthreads();

        if (ck + 2 < NCH) load_chunk(ck + 2, pst);
        CP_COMMIT();

        const uint32_t ah_s = sb + st*STG4;
        const uint32_t al_s = ah_s + TSTG;
        const uint32_t bh_s = ah_s + 2*TSTG;
        const uint32_t bl_s = ah_s + 3*TSTG;

#pragma unroll
        for (int ks = 0; ks < 4; ks++) {
            uint32_t ah[4][4], al[4][4], bh[2][4], bl[2][4];
#pragma unroll
            for (int mi = 0; mi < 4; mi++) {
                int row = a_row + mi*16;
                int c   = ks*2 + a_coff;
                uint32_t off = row*128 + ((c ^ (row & 7)) << 4);
                LDSM4(ah[mi], ah_s + off);
                LDSM4(al[mi], al_s + off);
            }
#pragma unroll
            for (int p = 0; p < 2; p++) {
                int row = b_row + p*16;
                int c   = ks*2 + b_coff;
                uint32_t off = row*128 + ((c ^ (row & 7)) << 4);
                LDSM4(bh[p], bh_s + off);
                LDSM4(bl[p], bl_s + off);
            }
#pragma unroll
            for (int mi = 0; mi < 4; mi++)
#pragma unroll
                for (int ni = 0; ni < 4; ni++) {
                    const int q = ni >> 1, r = (ni & 1)*2;
                    MMA16816(acc[mi][ni], ah[mi], bh[q][r], bh[q][r+1]);
                    MMA16816(acc[mi][ni], ah[mi], bl[q][r], bl[q][r+1]);
                    MMA16816(acc[mi][ni], al[mi], bh[q][r], bh[q][r+1]);
                }
        }
        __syncthreads();
        st  = (st  + 1 == ST) ? 0 : st  + 1;
        pst = (pst + 1 == ST) ? 0 : pst + 1;
    }

    // epilogue: registers -> gmem fp32
    const int g = lane >> 2, tq = lane & 3;
#pragma unroll
    for (int mi = 0; mi < 4; mi++) {
#pragma unroll
        for (int ni = 0; ni < 4; ni++) {
            int row0 = mt*128 + wm*64 + mi*16 + g;
            int col  = nt*128 + wn*32 + ni*8 + tq*2;
            float bx = 0.f, by = 0.f;
            if (BIAS) { bx = bias[col]; by = bias[col+1]; }
            float2 v0 = { acc[mi][ni][0] + bx, acc[mi][ni][1] + by };
            float2 v1 = { acc[mi][ni][2] + bx, acc[mi][ni][3] + by };
            *(float2*)(C + (size_t)row0 * N + col)     = v0;
            *(float2*)(C + (size_t)(row0+8) * N + col) = v1;
        }
    }
}

// ---------------------------------------------------------------------------
// fp32 -> packed bf16 split conversions.  Row layout: [0:K]=hi, [K:2K]=lo
// ---------------------------------------------------------------------------
__global__ void conv_act(const float* __restrict__ X, __nv_bfloat16* __restrict__ Y,
                         int M, int K)
{
    size_t i = (size_t)blockIdx.x * blockDim.x + threadIdx.x;
    size_t tot = (size_t)M * (K/4);
    if (i >= tot) return;
    size_t m = i / (K/4); int k4 = (int)(i % (K/4)) * 4;
    float4 v = reinterpret_cast<const float4*>(X)[i];
    __nv_bfloat16 h0 = __float2bfloat16_rn(v.x), h1 = __float2bfloat16_rn(v.y);
    __nv_bfloat16 h2 = __float2bfloat16_rn(v.z), h3 = __float2bfloat16_rn(v.w);
    __nv_bfloat16 l0 = __float2bfloat16_rn(v.x - __bfloat162float(h0));
    __nv_bfloat16 l1 = __float2bfloat16_rn(v.y - __bfloat162float(h1));
    __nv_bfloat16 l2 = __float2bfloat16_rn(v.z - __bfloat162float(h2));
    __nv_bfloat16 l3 = __float2bfloat16_rn(v.w - __bfloat162float(h3));
    __nv_bfloat16* row = Y + m * (size_t)(2*K);
    __nv_bfloat162* p0 = (__nv_bfloat162*)(row + k4);
    __nv_bfloat162* p1 = (__nv_bfloat162*)(row + K + k4);
    p0[0] = __halves2bfloat162(h0, h1); p0[1] = __halves2bfloat162(h2, h3);
    p1[0] = __halves2bfloat162(l0, l1); p1[1] = __halves2bfloat162(l2, l3);
}

// weights: W[K,N] f32 -> Y[N, 2K] bf16 transposed: [0:K]=hi, [K:2K]=lo
__global__ void conv_wt(const float* __restrict__ W, __nv_bfloat16* __restrict__ Y,
                        int K, int N)
{
    __shared__ float t[32][33];
    int n0 = blockIdx.x * 32, k0 = blockIdx.y * 32;
    int tx = threadIdx.x, ty = threadIdx.y;
#pragma unroll
    for (int j = 0; j < 32; j += 8)
        t[ty+j][tx] = W[(size_t)(k0+ty+j) * N + n0 + tx];
    __syncthreads();
#pragma unroll
    for (int j = 0; j < 32; j += 8) {
        int n = n0 + ty + j, k = k0 + tx;
        float x = t[tx][ty+j];
        __nv_bfloat16 h = __float2bfloat16_rn(x);
        __nv_bfloat16 l = __float2bfloat16_rn(x - __bfloat162float(h));
        __nv_bfloat16* row = Y + (size_t)n * (2*K);
        row[k] = h; row[K + k] = l;
    }
}

// ---------------------------------------------------------------------------
// Fused dual attention.  K/V/Kip/Vip come as column slices of the quad
// projection buffer KVq[768, 5120].  Output written DIRECTLY as packed
// bf16 [hi|lo] rows into Ob (row stride KP) — feeds the out-proj GEMM.
// ---------------------------------------------------------------------------
#define CHQ      512
#define AT_WARPS 8
#define PS_STR   96

__global__ void __launch_bounds__(256, 2)
attn_k(const float* __restrict__ Q, const float* __restrict__ KVq,
       __nv_bfloat16* __restrict__ Ob)
{
    extern __shared__ float sm[];
    float* Ks  = sm;
    float* Vs  = Ks  + NKEY*DP;
    float* Kis = Vs  + NKEY*DP;
    float* Vis = Kis + NIP*DP;
    float* Ps  = Vis + NIP*DP;
    float* Pip = Ps  + AT_WARPS*2*PS_STR;

    const int b    = blockIdx.z;
    const int h    = blockIdx.y;
    const int ch   = blockIdx.x;
    const int tid  = threadIdx.x;
    const int w    = tid >> 5;
    const int lane = tid & 31;

    for (int idx = tid; idx < NKEY*DH; idx += 256) {
        int s = idx / DH, d = idx % DH;
        size_t src = (size_t)(b*NCTX + s)*NQ + h*DH + d;
        Ks[s*DP + d] = KVq[src];
        Vs[s*DP + d] = KVq[src + HS];
    }
    for (int idx = tid; idx < NIP*DH; idx += 256) {
        int s = idx / DH, d = idx % DH;
        size_t src = (size_t)(b*NCTX + NKEY + s)*NQ + h*DH + d;
        Kis[s*DP + d] = KVq[src + 2*HS];
        Vis[s*DP + d] = KVq[src + 3*HS];
    }
    __syncthreads();

    const float scale = 0.07905694150420949f;  // 1/sqrt(160)

    int  krow[3]; bool kval[3];
#pragma unroll
    for (int j = 0; j < 3; j++) {
        int s   = lane + 32*j;
        kval[j] = (s < NKEY);
        krow[j] = (kval[j] ? s : 0) * DP;
    }
    const int iprow = (lane < NIP ? lane : 0) * DP;

    for (int qp = w; qp < CHQ/2; qp += AT_WARPS) {
        const int    q0 = ch*CHQ + qp*2;
        const size_t r0 = ((size_t)b*SEQ + q0)*HS + h*DH;

        float qv0[5], qv1[5];
#pragma unroll
        for (int i = 0; i < 5; i++) {
            qv0[i] = Q[r0 +      lane + 32*i];
            qv1[i] = Q[r0 + HS + lane + 32*i];
        }

        float sc0[3] = {0.f,0.f,0.f}, sc1[3] = {0.f,0.f,0.f};
        float si0 = 0.f, si1 = 0.f;
#pragma unroll
        for (int i = 0; i < 5; i++) {
            float a0 = qv0[i], a1 = qv1[i];
#pragma unroll 8
            for (int dd = 0; dd < 32; dd++) {
                float qd0 = __shfl_sync(0xffffffffu, a0, dd);
                float qd1 = __shfl_sync(0xffffffffu, a1, dd);
                const float* kp = Ks + i*32 + dd;
                float k0 = kp[krow[0]], k1 = kp[krow[1]], k2 = kp[krow[2]];
                sc0[0] += qd0*k0; sc0[1] += qd0*k1; sc0[2] += qd0*k2;
                sc1[0] += qd1*k0; sc1[1] += qd1*k1; sc1[2] += qd1*k2;
                float kiv = Kis[iprow + i*32 + dd];
                si0 += qd0*kiv; si1 += qd1*kiv;
            }
        }

        float m0 = -1e30f, m1 = -1e30f;
#pragma unroll
        for (int j = 0; j < 3; j++) {
            sc0[j] = kval[j] ? sc0[j]*scale : -1e30f;
            sc1[j] = kval[j] ? sc1[j]*scale : -1e30f;
            m0 = fmaxf(m0, sc0[j]);
            m1 = fmaxf(m1, sc1[j]);
        }
#pragma unroll
        for (int off = 16; off >= 1; off >>= 1) {
            m0 = fmaxf(m0, __shfl_xor_sync(0xffffffffu, m0, off));
            m1 = fmaxf(m1, __shfl_xor_sync(0xffffffffu, m1, off));
        }
        float e0[3], e1[3], s0 = 0.f, s1 = 0.f;
#pragma unroll
        for (int j = 0; j < 3; j++) {
            e0[j] = __expf(sc0[j] - m0); s0 += e0[j];
            e1[j] = __expf(sc1[j] - m1); s1 += e1[j];
        }
#pragma unroll
        for (int off = 16; off >= 1; off >>= 1) {
            s0 += __shfl_xor_sync(0xffffffffu, s0, off);
            s1 += __shfl_xor_sync(0xffffffffu, s1, off);
        }
        const float inv0 = 1.f / s0, inv1 = 1.f / s1;

        __syncwarp();
        float* Prow0 = Ps + (w*2 + 0)*PS_STR;
        float* Prow1 = Ps + (w*2 + 1)*PS_STR;
#pragma unroll
        for (int j = 0; j < 3; j++) {
            Prow0[lane + 32*j] = e0[j] * inv0;
            Prow1[lane + 32*j] = e1[j] * inv1;
        }
        if (lane < NIP) {
            Pip[(w*2 + 0)*NIP + lane] = si0 * scale;
            Pip[(w*2 + 1)*NIP + lane] = si1 * scale;
        }
        __syncwarp();

        float pi0[NIP], pi1[NIP];
        {
            float mm0 = -1e30f, mm1 = -1e30f;
#pragma unroll
            for (int s = 0; s < NIP; s++) {
                pi0[s] = Pip[(w*2 + 0)*NIP + s]; mm0 = fmaxf(mm0, pi0[s]);
                pi1[s] = Pip[(w*2 + 1)*NIP + s]; mm1 = fmaxf(mm1, pi1[s]);
            }
            float ss0 = 0.f, ss1 = 0.f;
#pragma unroll
            for (int s = 0; s < NIP; s++) {
                pi0[s] = __expf(pi0[s] - mm0); ss0 += pi0[s];
                pi1[s] = __expf(pi1[s] - mm1); ss1 += pi1[s];
            }
            float is0 = 1.f/ss0, is1 = 1.f/ss1;
#pragma unroll
            for (int s = 0; s < NIP; s++) { pi0[s] *= is0; pi1[s] *= is1; }
        }

        float o0[5] = {0.f,0.f,0.f,0.f,0.f};
        float o1[5] = {0.f,0.f,0.f,0.f,0.f};
        for (int s = 0; s < NKEY; s++) {
            float p0 = Prow0[s], p1 = Prow1[s];
            const float* vp = Vs + s*DP + lane;
#pragma unroll
            for (int i = 0; i < 5; i++) {
                float v = vp[32*i];
                o0[i] += p0 * v;
                o1[i] += p1 * v;
            }
        }
#pragma unroll
        for (int s = 0; s < NIP; s++) {
            const float* vp = Vis + s*DP + lane;
#pragma unroll
            for (int i = 0; i < 5; i++) {
                float v = vp[32*i];
                o0[i] += pi0[s] * v;
                o1[i] += pi1[s] * v;
            }
        }

        // packed bf16 [hi|lo] output rows (row stride KP)
        const size_t ob0 = ((size_t)b*SEQ + q0)*KP + h*DH;
#pragma unroll
        for (int i = 0; i < 5; i++) {
            int d = lane + 32*i;
            float x0 = o0[i], x1 = o1[i];
            __nv_bfloat16 h0 = __float2bfloat16_rn(x0);
            __nv_bfloat16 h1 = __float2bfloat16_rn(x1);
            Ob[ob0 +        d] = h0;
            Ob[ob0 + HS   + d] = __float2bfloat16_rn(x0 - __bfloat162float(h0));
            Ob[ob0 + KP   + d] = h1;
            Ob[ob0 + KP+HS+ d] = __float2bfloat16_rn(x1 - __bfloat162float(h1));
        }
        __syncwarp();
    }
}

// ---------------------------------------------------------------------------
// Launch
// ---------------------------------------------------------------------------
static const int ATT_SMEM =
    (2*NKEY*DP + 2*NIP*DP + AT_WARPS*2*PS_STR + AT_WARPS*2*NIP) * (int)sizeof(float);

extern "C" void kernel_launch(void* const* d_in, const int* in_sizes, int n_in,
                              void* d_out, int out_size)
{
    const float* hs   = (const float*)d_in[0];
    const float* ehs  = (const float*)d_in[1];
    const float* w_q  = (const float*)d_in[2];
    const float* w_k  = (const float*)d_in[3];
    const float* w_v  = (const float*)d_in[4];
    const float* w_ki = (const float*)d_in[5];
    const float* w_vi = (const float*)d_in[6];
    const float* w_o  = (const float*)d_in[7];
    const float* b_o  = (const float*)d_in[8];
    float* out = (float*)d_out;

    float *Qb, *KVq;
    __nv_bfloat16 *Abf, *Wbf, *Ebf, *Wqf;
    cudaGetSymbolAddress((void**)&Qb,  g_Q);
    cudaGetSymbolAddress((void**)&KVq, g_KVq);
    cudaGetSymbolAddress((void**)&Abf, g_Ab);
    cudaGetSymbolAddress((void**)&Wbf, g_Wb);
    cudaGetSymbolAddress((void**)&Ebf, g_Eb);
    cudaGetSymbolAddress((void**)&Wqf, g_Wq);

    cudaFuncSetAttribute(attn_k, cudaFuncAttributeMaxDynamicSharedMemorySize, ATT_SMEM);
    cudaFuncSetAttribute(mma_gemm<HS,false>,     cudaFuncAttributeMaxDynamicSharedMemorySize, MMA_SMEM);
    cudaFuncSetAttribute(mma_gemm<HS,true>,      cudaFuncAttributeMaxDynamicSharedMemorySize, MMA_SMEM);
    cudaFuncSetAttribute(mma_gemm<CROSSD,false>, cudaFuncAttributeMaxDynamicSharedMemorySize, MMA_SMEM);

    const int CT = 256;
    const size_t totA = (size_t)MQ * (HS/4);
    dim3 gm(HS/128, MQ/128);   // (10, 256)

    // ---- Q = hidden @ w_q  (bf16-split HMMA) ----
    conv_act<<<(unsigned)((totA + CT-1)/CT), CT>>>(hs, Abf, MQ, HS);
    conv_wt<<<dim3(HS/32, HS/32), dim3(32, 8)>>>(w_q, Wbf, HS, HS);
    mma_gemm<HS,false><<<gm, 256, MMA_SMEM>>>(Abf, Wbf, nullptr, Qb, HS);

    // ---- quad projection: [K|V|Kip|Vip] = ehs @ [w_k|w_v|w_ki|w_vi] ----
    const size_t totE = (size_t)(BATCH*NCTX) * (CROSSD/4);
    conv_act<<<(unsigned)((totE + CT-1)/CT), CT>>>(ehs, Ebf, BATCH*NCTX, CROSSD);
    dim3 gw(HS/32, CROSSD/32);
    conv_wt<<<gw, dim3(32, 8)>>>(w_k,  Wqf,                       CROSSD, HS);
    conv_wt<<<gw, dim3(32, 8)>>>(w_v,  Wqf + (size_t)HS*KPE,      CROSSD, HS);
    conv_wt<<<gw, dim3(32, 8)>>>(w_ki, Wqf + (size_t)2*HS*KPE,    CROSSD, HS);
    conv_wt<<<gw, dim3(32, 8)>>>(w_vi, Wqf + (size_t)3*HS*KPE,    CROSSD, HS);
    dim3 gq(NQ/128, MEPAD/128);   // (40, 6)
    mma_gemm<CROSSD,false><<<gq, 256, MMA_SMEM>>>(Ebf, Wqf, nullptr, KVq, NQ);

    // ---- fused dual attention -> packed bf16 activations ----
    dim3 ga(SEQ/CHQ, HEADS, BATCH);
    attn_k<<<ga, 256, ATT_SMEM>>>(Qb, KVq, Abf);

    // ---- out = attn @ w_out + b  (bf16-split HMMA) ----
    conv_wt<<<dim3(HS/32, HS/32), dim3(32, 8)>>>(w_o, Wbf, HS, HS);
    mma_gemm<HS,true><<<gm, 256, MMA_SMEM>>>(Abf, Wbf, b_o, out, HS);
}

// round 11
// speedup vs baseline: 2.8002x; 1.1955x over previous
#include <cuda.h>
#include <cuda_runtime.h>
#include <cuda_fp16.h>
#include <math.h>
#include <stdint.h>

// ---------------------------------------------------------------------------
// Problem constants
// ---------------------------------------------------------------------------
#define BATCH   8
#define SEQ     4096
#define HS      1280
#define HEADS   8
#define DH      160
#define NKEY    77
#define NIP     4
#define NCTX    81               // 77 text + 4 ip rows per batch
#define NKALL   81               // all keys resident per (b,h)
#define CROSSD  2048
#define MQ      (BATCH*SEQ)      // 32768
#define NQ      (4*HS)           // 5120  quad projection output columns
#define MEPAD   768              // 648 ctx rows padded to 6 CTA tiles

// Scratch device globals (allocation-free workaround)
__device__ float  g_Q[MQ * HS];                    // Q projection (f32)
__device__ float  g_KVq[MEPAD * NQ];               // quad proj out [K|V|Kip|Vip]
__device__ __half g_Ah[(size_t)MQ * HS];           // fp16 activations (hs, then attn out)
__device__ __half g_Wh[(size_t)HS * 2*HS];         // fp16 weight^T [hi|lo] (w_q, then w_o)
__device__ __half g_Eh[(size_t)MEPAD * CROSSD];    // fp16 ehs (rows 648+ stay zero)
__device__ __half g_Wq[(size_t)NQ * 2*CROSSD];     // fp16 quad weight^T [hi|lo]

// ---------------------------------------------------------------------------
// PTX helpers (portable sm_80+ ISA only)
// ---------------------------------------------------------------------------
__device__ __forceinline__ uint32_t smem_u32(const void* p) {
    uint32_t a;
    asm("{ .reg .u64 t; cvta.to.shared.u64 t, %1; cvt.u32.u64 %0, t; }"
        : "=r"(a) : "l"(p));
    return a;
}

#define CP_ASYNC16(dst, src) \
    asm volatile("cp.async.cg.shared.global [%0], [%1], 16;" \
        :: "r"(dst), "l"(src) : "memory")
#define CP_COMMIT() asm volatile("cp.async.commit_group;" ::: "memory")
#define CP_WAIT(n)  asm volatile("cp.async.wait_group %0;" :: "n"(n) : "memory")

#define LDSM4(r, addr) \
    asm volatile("ldmatrix.sync.aligned.m8n8.x4.shared.b16 {%0,%1,%2,%3}, [%4];" \
        : "=r"((r)[0]), "=r"((r)[1]), "=r"((r)[2]), "=r"((r)[3]) : "r"(addr))

#define MMA16816H(d, a, b0, b1) \
    asm volatile("mma.sync.aligned.m16n8k16.row.col.f32.f16.f16.f32 " \
        "{%0,%1,%2,%3}, {%4,%5,%6,%7}, {%8,%9}, {%0,%1,%2,%3};" \
        : "+f"((d)[0]), "+f"((d)[1]), "+f"((d)[2]), "+f"((d)[3]) \
        : "r"((a)[0]), "r"((a)[1]), "r"((a)[2]), "r"((a)[3]), "r"(b0), "r"(b1))

// ---------------------------------------------------------------------------
// fp16 2-term tensor-core GEMM:
//   C[M,N](f32) = A_fp16[M,KD] @ (Bhi + Blo)_fp16[N,KD]^T
// A plain fp16 (row stride KD); B packed [hi(0:KD) | lo(KD:2KD)] (stride 2KD).
// Error = A rounding only (~1.4e-4 RMS rel); B side exact to ~2^-21.
// CTA tile 128x128, K chunk 64 (128B SW128-swizzled rows), 4-stage pipeline.
// ---------------------------------------------------------------------------
#define KC    64
#define TSTG  16384                 // one 128x64 fp16 tile
#define STG3  (3*TSTG)              // 49152 per stage (A, Bhi, Blo)
#define MMA_SMEM (1024 + 4*STG3)    // 197632

template<int KD, bool BIAS>
__global__ void __launch_bounds__(256, 1)
mma_gemm2(const __half* __restrict__ Ag, const __half* __restrict__ Bg,
          const float* __restrict__ bias, float* __restrict__ C, int N)
{
    constexpr int NCH  = KD/KC;
    constexpr int BSTR = 2*KD;
    extern __shared__ char dsm[];
    const uint32_t sb = (smem_u32(dsm) + 1023u) & ~1023u;
    const int tid  = threadIdx.x;
    const int lane = tid & 31;
    const int wid  = tid >> 5;
    const int wm   = wid >> 2;        // 0..1  (64-row slab)
    const int wn   = wid & 3;         // 0..3  (32-col slab)
    const int mt   = blockIdx.y, nt = blockIdx.x;

    const __half* Abase = Ag + (size_t)(mt*128) * KD;
    const __half* Bbase = Bg + (size_t)(nt*128) * BSTR;

    // cp.async loader: per tile, 4 x 16B per thread (1024 chunks / 256 thr)
    int ld_row[4], ld_sw[4], ld_c8[4];
#pragma unroll
    for (int i = 0; i < 4; i++) {
        int idx   = tid + i*256;
        ld_row[i] = idx >> 3;
        int c     = idx & 7;
        ld_c8[i]  = c * 8;
        ld_sw[i]  = (c ^ (ld_row[i] & 7)) << 4;
    }

    auto load_chunk = [&](int ck, int st) {
        const uint32_t s0 = sb + st*STG3;
#pragma unroll
        for (int i = 0; i < 4; i++)
            CP_ASYNC16(s0 + ld_row[i]*128 + ld_sw[i],
                       Abase + (size_t)ld_row[i]*KD + ck*KC + ld_c8[i]);
#pragma unroll
        for (int i = 0; i < 4; i++)
            CP_ASYNC16(s0 + TSTG + ld_row[i]*128 + ld_sw[i],
                       Bbase + (size_t)ld_row[i]*BSTR + ck*KC + ld_c8[i]);
#pragma unroll
        for (int i = 0; i < 4; i++)
            CP_ASYNC16(s0 + 2*TSTG + ld_row[i]*128 + ld_sw[i],
                       Bbase + (size_t)ld_row[i]*BSTR + KD + ck*KC + ld_c8[i]);
    };

    float acc[4][4][4];
#pragma unroll
    for (int mi = 0; mi < 4; mi++)
#pragma unroll
        for (int ni = 0; ni < 4; ni++)
#pragma unroll
            for (int j = 0; j < 4; j++) acc[mi][ni][j] = 0.f;

    // ldmatrix lane addressing
    const int a_row  = wm*64 + (lane & 15);                        // + mi*16
    const int b_row  = wn*32 + ((lane >> 3) >> 1)*8 + (lane & 7);  // + p*16
    const int a_coff = lane >> 4;
    const int b_coff = (lane >> 3) & 1;

    // prologue: fill 3 stages
    load_chunk(0, 0); CP_COMMIT();
    load_chunk(1, 1); CP_COMMIT();
    load_chunk(2, 2); CP_COMMIT();

    for (int ck = 0; ck < NCH; ck++) {
        CP_WAIT(2);
        __syncthreads();

        if (ck + 3 < NCH) load_chunk(ck + 3, (ck + 3) & 3);
        CP_COMMIT();

        const int st = ck & 3;
        const uint32_t a_s  = sb + st*STG3;
        const uint32_t bh_s = a_s + TSTG;
        const uint32_t bl_s = a_s + 2*TSTG;

#pragma unroll
        for (int ks = 0; ks < 4; ks++) {
            uint32_t ah[4][4], bh[2][4], bl[2][4];
#pragma unroll
            for (int mi = 0; mi < 4; mi++) {
                int row = a_row + mi*16;
                int c   = ks*2 + a_coff;
                LDSM4(ah[mi], a_s + row*128 + ((c ^ (row & 7)) << 4));
            }
#pragma unroll
            for (int p = 0; p < 2; p++) {
                int row = b_row + p*16;
                int c   = ks*2 + b_coff;
                uint32_t off = row*128 + ((c ^ (row & 7)) << 4);
                LDSM4(bh[p], bh_s + off);
                LDSM4(bl[p], bl_s + off);
            }
#pragma unroll
            for (int mi = 0; mi < 4; mi++)
#pragma unroll
                for (int ni = 0; ni < 4; ni++) {
                    const int q = ni >> 1, r = (ni & 1)*2;
                    MMA16816H(acc[mi][ni], ah[mi], bh[q][r], bh[q][r+1]);
                    MMA16816H(acc[mi][ni], ah[mi], bl[q][r], bl[q][r+1]);
                }
        }
        __syncthreads();
    }

    // epilogue: registers -> gmem fp32
    const int g = lane >> 2, tq = lane & 3;
#pragma unroll
    for (int mi = 0; mi < 4; mi++) {
#pragma unroll
        for (int ni = 0; ni < 4; ni++) {
            int row0 = mt*128 + wm*64 + mi*16 + g;
            int col  = nt*128 + wn*32 + ni*8 + tq*2;
            float bx = 0.f, by = 0.f;
            if (BIAS) { bx = bias[col]; by = bias[col+1]; }
            float2 v0 = { acc[mi][ni][0] + bx, acc[mi][ni][1] + by };
            float2 v1 = { acc[mi][ni][2] + bx, acc[mi][ni][3] + by };
            *(float2*)(C + (size_t)row0 * N + col)     = v0;
            *(float2*)(C + (size_t)(row0+8) * N + col) = v1;
        }
    }
}

// ---------------------------------------------------------------------------
// fp32 -> fp16 conversions
// ---------------------------------------------------------------------------
__global__ void conv_act_h(const float* __restrict__ X, __half* __restrict__ Y,
                           size_t tot4)
{
    size_t i = (size_t)blockIdx.x * blockDim.x + threadIdx.x;
    if (i >= tot4) return;
    float4 v = reinterpret_cast<const float4*>(X)[i];
    __half2* p = (__half2*)(Y + i*4);
    p[0] = __floats2half2_rn(v.x, v.y);
    p[1] = __floats2half2_rn(v.z, v.w);
}

// weights: W[K,N] f32 -> Y[N, 2K] fp16 transposed: [0:K]=hi, [K:2K]=lo
__global__ void conv_wt_h(const float* __restrict__ W, __half* __restrict__ Y,
                          int K, int N)
{
    __shared__ float t[32][33];
    int n0 = blockIdx.x * 32, k0 = blockIdx.y * 32;
    int tx = threadIdx.x, ty = threadIdx.y;
#pragma unroll
    for (int j = 0; j < 32; j += 8)
        t[ty+j][tx] = W[(size_t)(k0+ty+j) * N + n0 + tx];
    __syncthreads();
#pragma unroll
    for (int j = 0; j < 32; j += 8) {
        int n = n0 + ty + j, k = k0 + tx;
        float x = t[tx][ty+j];
        __half h = __float2half_rn(x);
        __half l = __float2half_rn(x - __half2float(h));
        __half* row = Y + (size_t)n * (2*K);
        row[k] = h; row[K + k] = l;
    }
}

// ---------------------------------------------------------------------------
// Fused dual attention, vectorized.
//   Ks[81][164]  : text keys 0..76, ip keys 77..80 (float4-aligned stride)
//   Vt[160][92]  : V TRANSPOSED (d-major) incl. ip rows; cols 81..91 zeroed
//   Ps[32][92]   : per-(warp,query) prob rows: [0:77] text, [77:81] ip, [81:88]=0
// Output written as plain fp16 rows into Oh (feeds 2-term out-proj GEMM).
// ---------------------------------------------------------------------------
#define CHQ      1024
#define AT_WARPS 16
#define SDIM     164
#define VDIM     92

#define ATT_SMEM ((NKALL*SDIM + DH*VDIM + 2*AT_WARPS*VDIM + 2*AT_WARPS*4) * 4)

__global__ void __launch_bounds__(512, 1)
attn_k(const float* __restrict__ Q, const float* __restrict__ KVq,
       __half* __restrict__ Oh)
{
    extern __shared__ float sm[];
    float* Ks  = sm;                        // 81 x 164
    float* Vt  = Ks + NKALL*SDIM;           // 160 x 92
    float* Ps  = Vt + DH*VDIM;              // 32 x 92
    float* Pip = Ps + 2*AT_WARPS*VDIM;      // 32 x 4

    const int b    = blockIdx.z;
    const int h    = blockIdx.y;
    const int ch   = blockIdx.x;
    const int tid  = threadIdx.x;
    const int w    = tid >> 5;
    const int lane = tid & 31;

    // zero Vt pad columns 81..91 (never loaded; read by unified PV)
    for (int idx = tid; idx < DH*11; idx += 512) {
        int d = idx / 11, s = 81 + idx % 11;
        Vt[d*VDIM + s] = 0.f;
    }
    // cooperative K/V loads; V transposed
    for (int idx = tid; idx < NKALL*DH; idx += 512) {
        int s = idx / DH, d = idx % DH;
        size_t src = (size_t)(b*NCTX + s)*NQ + h*DH + d;
        float kv = (s < NKEY) ? KVq[src]      : KVq[src + 2*HS];
        float vv = (s < NKEY) ? KVq[src + HS] : KVq[src + 3*HS];
        Ks[s*SDIM + d] = kv;
        Vt[d*VDIM + s] = vv;
    }
    __syncthreads();

    const float scale = 0.07905694150420949f;  // 1/sqrt(160)

    int  krow[3]; bool kval[3];
#pragma unroll
    for (int j = 0; j < 3; j++) {
        int s   = lane + 32*j;
        kval[j] = (s < NKEY);
        krow[j] = (kval[j] ? s : 0) * SDIM;
    }
    const int iprow = (NKEY + (lane & 3)) * SDIM;

    float* Prow0 = Ps + (w*2 + 0)*VDIM;
    float* Prow1 = Ps + (w*2 + 1)*VDIM;

    for (int qp = w; qp < CHQ/2; qp += AT_WARPS) {
        const int    q0 = ch*CHQ + qp*2;
        const size_t r0 = ((size_t)b*SEQ + q0)*HS + h*DH;

        float qv0[5], qv1[5];
#pragma unroll
        for (int i = 0; i < 5; i++) {
            qv0[i] = Q[r0 +      lane + 32*i];
            qv1[i] = Q[r0 + HS + lane + 32*i];
        }

        float sc0[3] = {0.f,0.f,0.f}, sc1[3] = {0.f,0.f,0.f};
        float si0 = 0.f, si1 = 0.f;
#pragma unroll
        for (int i = 0; i < 5; i++) {
            float a0 = qv0[i], a1 = qv1[i];
#pragma unroll
            for (int d4 = 0; d4 < 8; d4++) {
                const int doff = i*32 + d4*4;
                float4 k0 = *(const float4*)&Ks[krow[0] + doff];
                float4 k1 = *(const float4*)&Ks[krow[1] + doff];
                float4 k2 = *(const float4*)&Ks[krow[2] + doff];
                float4 ki = *(const float4*)&Ks[iprow   + doff];
#pragma unroll
                for (int c = 0; c < 4; c++) {
                    float q0v = __shfl_sync(0xffffffffu, a0, d4*4 + c);
                    float q1v = __shfl_sync(0xffffffffu, a1, d4*4 + c);
                    float kk0 = (&k0.x)[c], kk1 = (&k1.x)[c];
                    float kk2 = (&k2.x)[c], kki = (&ki.x)[c];
                    sc0[0] += q0v*kk0; sc0[1] += q0v*kk1; sc0[2] += q0v*kk2;
                    si0    += q0v*kki;
                    sc1[0] += q1v*kk0; sc1[1] += q1v*kk1; sc1[2] += q1v*kk2;
                    si1    += q1v*kki;
                }
            }
        }

        // ---- text softmax (warp-wide over 77 keys) ----
        float m0 = -1e30f, m1 = -1e30f;
#pragma unroll
        for (int j = 0; j < 3; j++) {
            sc0[j] = kval[j] ? sc0[j]*scale : -1e30f;
            sc1[j] = kval[j] ? sc1[j]*scale : -1e30f;
            m0 = fmaxf(m0, sc0[j]);
            m1 = fmaxf(m1, sc1[j]);
        }
#pragma unroll
        for (int off = 16; off >= 1; off >>= 1) {
            m0 = fmaxf(m0, __shfl_xor_sync(0xffffffffu, m0, off));
            m1 = fmaxf(m1, __shfl_xor_sync(0xffffffffu, m1, off));
        }
        float e0[3], e1[3], s0 = 0.f, s1 = 0.f;
#pragma unroll
        for (int j = 0; j < 3; j++) {
            e0[j] = __expf(sc0[j] - m0); s0 += e0[j];
            e1[j] = __expf(sc1[j] - m1); s1 += e1[j];
        }
#pragma unroll
        for (int off = 16; off >= 1; off >>= 1) {
            s0 += __shfl_xor_sync(0xffffffffu, s0, off);
            s1 += __shfl_xor_sync(0xffffffffu, s1, off);
        }
        const float inv0 = 1.f / s0, inv1 = 1.f / s1;

        __syncwarp();
        // text probs (zeros land in slots 77..87 for invalid keys)
#pragma unroll
        for (int j = 0; j < 3; j++) {
            int s = lane + 32*j;
            if (s < 88) {
                Prow0[s] = e0[j] * inv0;
                Prow1[s] = e1[j] * inv1;
            }
        }
        if (lane < NIP) {
            Pip[(w*2 + 0)*4 + lane] = si0 * scale;
            Pip[(w*2 + 1)*4 + lane] = si1 * scale;
        }
        __syncwarp();

        // ---- ip softmax (4 keys, redundant per lane) ----
        float pi0[NIP], pi1[NIP];
        {
            float mm0 = -1e30f, mm1 = -1e30f;
#pragma unroll
            for (int s = 0; s < NIP; s++) {
                pi0[s] = Pip[(w*2 + 0)*4 + s]; mm0 = fmaxf(mm0, pi0[s]);
                pi1[s] = Pip[(w*2 + 1)*4 + s]; mm1 = fmaxf(mm1, pi1[s]);
            }
            float ss0 = 0.f, ss1 = 0.f;
#pragma unroll
            for (int s = 0; s < NIP; s++) {
                pi0[s] = __expf(pi0[s] - mm0); ss0 += pi0[s];
                pi1[s] = __expf(pi1[s] - mm1); ss1 += pi1[s];
            }
            float is0 = 1.f/ss0, is1 = 1.f/ss1;
#pragma unroll
            for (int s = 0; s < NIP; s++) { pi0[s] *= is0; pi1[s] *= is1; }
        }
        if (lane < NIP) {
            Prow0[NKEY + lane] = pi0[lane];
            Prow1[NKEY + lane] = pi1[lane];
        }
        __syncwarp();

        // ---- unified PV over 88 slots (float4 over keys, Vt transposed) ----
        float o0[5] = {0.f,0.f,0.f,0.f,0.f};
        float o1[5] = {0.f,0.f,0.f,0.f,0.f};
#pragma unroll 2
        for (int sb4 = 0; sb4 < 22; sb4++) {
            float4 p0 = *(const float4*)&Prow0[sb4*4];
            float4 p1 = *(const float4*)&Prow1[sb4*4];
#pragma unroll
            for (int i = 0; i < 5; i++) {
                float4 v = *(const float4*)&Vt[(lane + 32*i)*VDIM + sb4*4];
                o0[i] += p0.x*v.x + p0.y*v.y + p0.z*v.z + p0.w*v.w;
                o1[i] += p1.x*v.x + p1.y*v.y + p1.z*v.z + p1.w*v.w;
            }
        }

        // plain fp16 output rows (A-side of 2-term out-proj)
        const size_t ob0 = ((size_t)b*SEQ + q0)*HS + h*DH;
#pragma unroll
        for (int i = 0; i < 5; i++) {
            int d = lane + 32*i;
            Oh[ob0 +      d] = __float2half_rn(o0[i]);
            Oh[ob0 + HS + d] = __float2half_rn(o1[i]);
        }
        __syncwarp();
    }
}

// ---------------------------------------------------------------------------
// Launch
// ---------------------------------------------------------------------------
extern "C" void kernel_launch(void* const* d_in, const int* in_sizes, int n_in,
                              void* d_out, int out_size)
{
    const float* hs   = (const float*)d_in[0];
    const float* ehs  = (const float*)d_in[1];
    const float* w_q  = (const float*)d_in[2];
    const float* w_k  = (const float*)d_in[3];
    const float* w_v  = (const float*)d_in[4];
    const float* w_ki = (const float*)d_in[5];
    const float* w_vi = (const float*)d_in[6];
    const float* w_o  = (const float*)d_in[7];
    const float* b_o  = (const float*)d_in[8];
    float* out = (float*)d_out;

    float *Qb, *KVq;
    __half *Ah, *Wh, *Eh, *Wq;
    cudaGetSymbolAddress((void**)&Qb,  g_Q);
    cudaGetSymbolAddress((void**)&KVq, g_KVq);
    cudaGetSymbolAddress((void**)&Ah,  g_Ah);
    cudaGetSymbolAddress((void**)&Wh,  g_Wh);
    cudaGetSymbolAddress((void**)&Eh,  g_Eh);
    cudaGetSymbolAddress((void**)&Wq,  g_Wq);

    cudaFuncSetAttribute(attn_k, cudaFuncAttributeMaxDynamicSharedMemorySize, ATT_SMEM);
    cudaFuncSetAttribute(mma_gemm2<HS,false>,     cudaFuncAttributeMaxDynamicSharedMemorySize, MMA_SMEM);
    cudaFuncSetAttribute(mma_gemm2<HS,true>,      cudaFuncAttributeMaxDynamicSharedMemorySize, MMA_SMEM);
    cudaFuncSetAttribute(mma_gemm2<CROSSD,false>, cudaFuncAttributeMaxDynamicSharedMemorySize, MMA_SMEM);

    const int CT = 256;
    dim3 gm(HS/128, MQ/128);   // (10, 256)

    // ---- Q = hidden @ w_q  (fp16 2-term HMMA) ----
    const size_t totA = (size_t)MQ * (HS/4);
    conv_act_h<<<(unsigned)((totA + CT-1)/CT), CT>>>(hs, Ah, totA);
    conv_wt_h<<<dim3(HS/32, HS/32), dim3(32, 8)>>>(w_q, Wh, HS, HS);
    mma_gemm2<HS,false><<<gm, 256, MMA_SMEM>>>(Ah, Wh, nullptr, Qb, HS);

    // ---- quad projection: [K|V|Kip|Vip] = ehs @ [w_k|w_v|w_ki|w_vi] ----
    const size_t totE = (size_t)(BATCH*NCTX) * (CROSSD/4);
    conv_act_h<<<(unsigned)((totE + CT-1)/CT), CT>>>(ehs, Eh, totE);
    dim3 gw(HS/32, CROSSD/32);
    conv_wt_h<<<gw, dim3(32, 8)>>>(w_k,  Wq,                           CROSSD, HS);
    conv_wt_h<<<gw, dim3(32, 8)>>>(w_v,  Wq + (size_t)HS*2*CROSSD,     CROSSD, HS);
    conv_wt_h<<<gw, dim3(32, 8)>>>(w_ki, Wq + (size_t)2*HS*2*CROSSD,   CROSSD, HS);
    conv_wt_h<<<gw, dim3(32, 8)>>>(w_vi, Wq + (size_t)3*HS*2*CROSSD,   CROSSD, HS);
    dim3 gq(NQ/128, MEPAD/128);   // (40, 6)
    mma_gemm2<CROSSD,false><<<gq, 256, MMA_SMEM>>>(Eh, Wq, nullptr, KVq, NQ);

    // ---- out-proj weight conversion (independent; before attention) ----
    conv_wt_h<<<dim3(HS/32, HS/32), dim3(32, 8)>>>(w_o, Wh, HS, HS);

    // ---- fused dual attention -> fp16 activations (overwrites g_Ah) ----
    dim3 ga(SEQ/CHQ, HEADS, BATCH);   // (4, 8, 8)
    attn_k<<<ga, 512, ATT_SMEM>>>(Qb, KVq, Ah);

    // ---- out = attn @ w_out + b  (fp16 2-term HMMA) ----
    mma_gemm2<HS,true><<<gm, 256, MMA_SMEM>>>(Ah, Wh, b_o, out, HS);
}

// round 12
// speedup vs baseline: 4.0045x; 1.4301x over previous
#include <cuda.h>
#include <cuda_runtime.h>
#include <cuda_fp16.h>
#include <math.h>
#include <stdint.h>

// ---------------------------------------------------------------------------
// Problem constants
// ---------------------------------------------------------------------------
#define BATCH   8
#define SEQ     4096
#define HS      1280
#define HEADS   8
#define DH      160
#define NKEY    77
#define NIP     4
#define NCTX    81               // 77 text + 4 ip rows per batch
#define NKALL   81               // all keys resident per (b,h)
#define CROSSD  2048
#define MQ      (BATCH*SEQ)      // 32768
#define NQ      (4*HS)           // 5120  quad projection output columns
#define MEPAD   768              // 648 ctx rows padded to 6 CTA tiles

// Scratch device globals (allocation-free workaround)
__device__ float  g_Q[MQ * HS];                    // Q projection (f32)
__device__ float  g_KVq[MEPAD * NQ];               // quad proj out [K|V|Kip|Vip]
__device__ __half g_Ah[(size_t)MQ * HS];           // fp16 activations (hs, then attn out)
__device__ __half g_Wh[(size_t)HS * HS];           // fp16 weight^T (w_q, then w_o)
__device__ __half g_Eh[(size_t)MEPAD * CROSSD];    // fp16 ehs (rows 648+ stay zero)
__device__ __half g_Wq[(size_t)NQ * CROSSD];       // fp16 quad weight^T

// ---------------------------------------------------------------------------
// PTX helpers (portable sm_80+ ISA only)
// ---------------------------------------------------------------------------
__device__ __forceinline__ uint32_t smem_u32(const void* p) {
    uint32_t a;
    asm("{ .reg .u64 t; cvta.to.shared.u64 t, %1; cvt.u32.u64 %0, t; }"
        : "=r"(a) : "l"(p));
    return a;
}

#define CP_ASYNC16(dst, src) \
    asm volatile("cp.async.cg.shared.global [%0], [%1], 16;" \
        :: "r"(dst), "l"(src) : "memory")
#define CP_COMMIT() asm volatile("cp.async.commit_group;" ::: "memory")
#define CP_WAIT(n)  asm volatile("cp.async.wait_group %0;" :: "n"(n) : "memory")

#define LDSM4(r, addr) \
    asm volatile("ldmatrix.sync.aligned.m8n8.x4.shared.b16 {%0,%1,%2,%3}, [%4];" \
        : "=r"((r)[0]), "=r"((r)[1]), "=r"((r)[2]), "=r"((r)[3]) : "r"(addr))

#define MMA16816H(d, a, b0, b1) \
    asm volatile("mma.sync.aligned.m16n8k16.row.col.f32.f16.f16.f32 " \
        "{%0,%1,%2,%3}, {%4,%5,%6,%7}, {%8,%9}, {%0,%1,%2,%3};" \
        : "+f"((d)[0]), "+f"((d)[1]), "+f"((d)[2]), "+f"((d)[3]) \
        : "r"((a)[0]), "r"((a)[1]), "r"((a)[2]), "r"((a)[3]), "r"(b0), "r"(b1))

// ---------------------------------------------------------------------------
// fp16 single-pass tensor-core GEMM:
//   C[M,N](f32) = A_fp16[M,KD] @ B_fp16[N,KD]^T     (fp32 accumulate)
// CTA tile 128x128, K chunk 64 (128B SW128-swizzled rows), 3-stage pipeline,
// 2 CTAs/SM (97 KB smem) for issue-latency hiding.
// ---------------------------------------------------------------------------
#define KC    64
#define TSTG  16384                 // one 128x64 fp16 tile
#define STG2  (2*TSTG)              // 32768 per stage (A, B)
#define MMA_SMEM (1024 + 3*STG2)    // 99328

template<int KD, bool BIAS>
__global__ void __launch_bounds__(256, 2)
mma_gemm1(const __half* __restrict__ Ag, const __half* __restrict__ Bg,
          const float* __restrict__ bias, float* __restrict__ C, int N)
{
    constexpr int NCH = KD/KC;
    extern __shared__ char dsm[];
    const uint32_t sb = (smem_u32(dsm) + 1023u) & ~1023u;
    const int tid  = threadIdx.x;
    const int lane = tid & 31;
    const int wid  = tid >> 5;
    const int wm   = wid >> 2;        // 0..1  (64-row slab)
    const int wn   = wid & 3;         // 0..3  (32-col slab)
    const int mt   = blockIdx.y, nt = blockIdx.x;

    const __half* Abase = Ag + (size_t)(mt*128) * KD;
    const __half* Bbase = Bg + (size_t)(nt*128) * KD;

    // cp.async loader: per tile, 4 x 16B per thread (1024 chunks / 256 thr)
    int ld_row[4], ld_sw[4], ld_c8[4];
#pragma unroll
    for (int i = 0; i < 4; i++) {
        int idx   = tid + i*256;
        ld_row[i] = idx >> 3;
        int c     = idx & 7;
        ld_c8[i]  = c * 8;
        ld_sw[i]  = (c ^ (ld_row[i] & 7)) << 4;
    }

    auto load_chunk = [&](int ck, int st) {
        const uint32_t s0 = sb + st*STG2;
#pragma unroll
        for (int i = 0; i < 4; i++)
            CP_ASYNC16(s0 + ld_row[i]*128 + ld_sw[i],
                       Abase + (size_t)ld_row[i]*KD + ck*KC + ld_c8[i]);
#pragma unroll
        for (int i = 0; i < 4; i++)
            CP_ASYNC16(s0 + TSTG + ld_row[i]*128 + ld_sw[i],
                       Bbase + (size_t)ld_row[i]*KD + ck*KC + ld_c8[i]);
    };

    float acc[4][4][4];
#pragma unroll
    for (int mi = 0; mi < 4; mi++)
#pragma unroll
        for (int ni = 0; ni < 4; ni++)
#pragma unroll
            for (int j = 0; j < 4; j++) acc[mi][ni][j] = 0.f;

    // ldmatrix lane addressing
    const int a_row  = wm*64 + (lane & 15);                        // + mi*16
    const int b_row  = wn*32 + ((lane >> 3) >> 1)*8 + (lane & 7);  // + p*16
    const int a_coff = lane >> 4;
    const int b_coff = (lane >> 3) & 1;

    // prologue: fill 2 of 3 stages
    load_chunk(0, 0); CP_COMMIT();
    load_chunk(1, 1); CP_COMMIT();

    int st = 0, pst = 2;
    for (int ck = 0; ck < NCH; ck++) {
        CP_WAIT(1);
        __syncthreads();

        if (ck + 2 < NCH) load_chunk(ck + 2, pst);
        CP_COMMIT();

        const uint32_t a_s = sb + st*STG2;
        const uint32_t b_s = a_s + TSTG;

#pragma unroll
        for (int ks = 0; ks < 4; ks++) {
            uint32_t ah[4][4], bh[2][4];
#pragma unroll
            for (int mi = 0; mi < 4; mi++) {
                int row = a_row + mi*16;
                int c   = ks*2 + a_coff;
                LDSM4(ah[mi], a_s + row*128 + ((c ^ (row & 7)) << 4));
            }
#pragma unroll
            for (int p = 0; p < 2; p++) {
                int row = b_row + p*16;
                int c   = ks*2 + b_coff;
                LDSM4(bh[p], b_s + row*128 + ((c ^ (row & 7)) << 4));
            }
#pragma unroll
            for (int mi = 0; mi < 4; mi++)
#pragma unroll
                for (int ni = 0; ni < 4; ni++) {
                    const int q = ni >> 1, r = (ni & 1)*2;
                    MMA16816H(acc[mi][ni], ah[mi], bh[q][r], bh[q][r+1]);
                }
        }
        __syncthreads();
        st  = (st  + 1 == 3) ? 0 : st  + 1;
        pst = (pst + 1 == 3) ? 0 : pst + 1;
    }

    // epilogue: registers -> gmem fp32
    const int g = lane >> 2, tq = lane & 3;
#pragma unroll
    for (int mi = 0; mi < 4; mi++) {
#pragma unroll
        for (int ni = 0; ni < 4; ni++) {
            int row0 = mt*128 + wm*64 + mi*16 + g;
            int col  = nt*128 + wn*32 + ni*8 + tq*2;
            float bx = 0.f, by = 0.f;
            if (BIAS) { bx = bias[col]; by = bias[col+1]; }
            float2 v0 = { acc[mi][ni][0] + bx, acc[mi][ni][1] + by };
            float2 v1 = { acc[mi][ni][2] + bx, acc[mi][ni][3] + by };
            *(float2*)(C + (size_t)row0 * N + col)     = v0;
            *(float2*)(C + (size_t)(row0+8) * N + col) = v1;
        }
    }
}

// ---------------------------------------------------------------------------
// fp32 -> fp16 conversions
// ---------------------------------------------------------------------------
__global__ void conv_act_h(const float* __restrict__ X, __half* __restrict__ Y,
                           size_t tot4)
{
    size_t i = (size_t)blockIdx.x * blockDim.x + threadIdx.x;
    if (i >= tot4) return;
    float4 v = reinterpret_cast<const float4*>(X)[i];
    __half2* p = (__half2*)(Y + i*4);
    p[0] = __floats2half2_rn(v.x, v.y);
    p[1] = __floats2half2_rn(v.z, v.w);
}

// weights: W[K,N] f32 -> Y[N,K] fp16 transposed
__global__ void conv_wt_h(const float* __restrict__ W, __half* __restrict__ Y,
                          int K, int N)
{
    __shared__ float t[32][33];
    int n0 = blockIdx.x * 32, k0 = blockIdx.y * 32;
    int tx = threadIdx.x, ty = threadIdx.y;
#pragma unroll
    for (int j = 0; j < 32; j += 8)
        t[ty+j][tx] = W[(size_t)(k0+ty+j) * N + n0 + tx];
    __syncthreads();
#pragma unroll
    for (int j = 0; j < 32; j += 8) {
        int n = n0 + ty + j, k = k0 + tx;
        Y[(size_t)n * K + k] = __float2half_rn(t[tx][ty+j]);
    }
}

// ---------------------------------------------------------------------------
// Fused dual attention, vectorized (unchanged from round 11).
// ---------------------------------------------------------------------------
#define CHQ      1024
#define AT_WARPS 16
#define SDIM     164
#define VDIM     92

#define ATT_SMEM ((NKALL*SDIM + DH*VDIM + 2*AT_WARPS*VDIM + 2*AT_WARPS*4) * 4)

__global__ void __launch_bounds__(512, 1)
attn_k(const float* __restrict__ Q, const float* __restrict__ KVq,
       __half* __restrict__ Oh)
{
    extern __shared__ float sm[];
    float* Ks  = sm;                        // 81 x 164
    float* Vt  = Ks + NKALL*SDIM;           // 160 x 92
    float* Ps  = Vt + DH*VDIM;              // 32 x 92
    float* Pip = Ps + 2*AT_WARPS*VDIM;      // 32 x 4

    const int b    = blockIdx.z;
    const int h    = blockIdx.y;
    const int ch   = blockIdx.x;
    const int tid  = threadIdx.x;
    const int w    = tid >> 5;
    const int lane = tid & 31;

    for (int idx = tid; idx < DH*11; idx += 512) {
        int d = idx / 11, s = 81 + idx % 11;
        Vt[d*VDIM + s] = 0.f;
    }
    for (int idx = tid; idx < NKALL*DH; idx += 512) {
        int s = idx / DH, d = idx % DH;
        size_t src = (size_t)(b*NCTX + s)*NQ + h*DH + d;
        float kv = (s < NKEY) ? KVq[src]      : KVq[src + 2*HS];
        float vv = (s < NKEY) ? KVq[src + HS] : KVq[src + 3*HS];
        Ks[s*SDIM + d] = kv;
        Vt[d*VDIM + s] = vv;
    }
    __syncthreads();

    const float scale = 0.07905694150420949f;  // 1/sqrt(160)

    int  krow[3]; bool kval[3];
#pragma unroll
    for (int j = 0; j < 3; j++) {
        int s   = lane + 32*j;
        kval[j] = (s < NKEY);
        krow[j] = (kval[j] ? s : 0) * SDIM;
    }
    const int iprow = (NKEY + (lane & 3)) * SDIM;

    float* Prow0 = Ps + (w*2 + 0)*VDIM;
    float* Prow1 = Ps + (w*2 + 1)*VDIM;

    for (int qp = w; qp < CHQ/2; qp += AT_WARPS) {
        const int    q0 = ch*CHQ + qp*2;
        const size_t r0 = ((size_t)b*SEQ + q0)*HS + h*DH;

        float qv0[5], qv1[5];
#pragma unroll
        for (int i = 0; i < 5; i++) {
            qv0[i] = Q[r0 +      lane + 32*i];
            qv1[i] = Q[r0 + HS + lane + 32*i];
        }

        float sc0[3] = {0.f,0.f,0.f}, sc1[3] = {0.f,0.f,0.f};
        float si0 = 0.f, si1 = 0.f;
#pragma unroll
        for (int i = 0; i < 5; i++) {
            float a0 = qv0[i], a1 = qv1[i];
#pragma unroll
            for (int d4 = 0; d4 < 8; d4++) {
                const int doff = i*32 + d4*4;
                float4 k0 = *(const float4*)&Ks[krow[0] + doff];
                float4 k1 = *(const float4*)&Ks[krow[1] + doff];
                float4 k2 = *(const float4*)&Ks[krow[2] + doff];
                float4 ki = *(const float4*)&Ks[iprow   + doff];
#pragma unroll
                for (int c = 0; c < 4; c++) {
                    float q0v = __shfl_sync(0xffffffffu, a0, d4*4 + c);
                    float q1v = __shfl_sync(0xffffffffu, a1, d4*4 + c);
                    float kk0 = (&k0.x)[c], kk1 = (&k1.x)[c];
                    float kk2 = (&k2.x)[c], kki = (&ki.x)[c];
                    sc0[0] += q0v*kk0; sc0[1] += q0v*kk1; sc0[2] += q0v*kk2;
                    si0    += q0v*kki;
                    sc1[0] += q1v*kk0; sc1[1] += q1v*kk1; sc1[2] += q1v*kk2;
                    si1    += q1v*kki;
                }
            }
        }

        // ---- text softmax (warp-wide over 77 keys) ----
        float m0 = -1e30f, m1 = -1e30f;
#pragma unroll
        for (int j = 0; j < 3; j++) {
            sc0[j] = kval[j] ? sc0[j]*scale : -1e30f;
            sc1[j] = kval[j] ? sc1[j]*scale : -1e30f;
            m0 = fmaxf(m0, sc0[j]);
            m1 = fmaxf(m1, sc1[j]);
        }
#pragma unroll
        for (int off = 16; off >= 1; off >>= 1) {
            m0 = fmaxf(m0, __shfl_xor_sync(0xffffffffu, m0, off));
            m1 = fmaxf(m1, __shfl_xor_sync(0xffffffffu, m1, off));
        }
        float e0[3], e1[3], s0 = 0.f, s1 = 0.f;
#pragma unroll
        for (int j = 0; j < 3; j++) {
            e0[j] = __expf(sc0[j] - m0); s0 += e0[j];
            e1[j] = __expf(sc1[j] - m1); s1 += e1[j];
        }
#pragma unroll
        for (int off = 16; off >= 1; off >>= 1) {
            s0 += __shfl_xor_sync(0xffffffffu, s0, off);
            s1 += __shfl_xor_sync(0xffffffffu, s1, off);
        }
        const float inv0 = 1.f / s0, inv1 = 1.f / s1;

        __syncwarp();
#pragma unroll
        for (int j = 0; j < 3; j++) {
            int s = lane + 32*j;
            if (s < 88) {
                Prow0[s] = e0[j] * inv0;
                Prow1[s] = e1[j] * inv1;
            }
        }
        if (lane < NIP) {
            Pip[(w*2 + 0)*4 + lane] = si0 * scale;
            Pip[(w*2 + 1)*4 + lane] = si1 * scale;
        }
        __syncwarp();

        // ---- ip softmax (4 keys, redundant per lane) ----
        float pi0[NIP], pi1[NIP];
        {
            float mm0 = -1e30f, mm1 = -1e30f;
#pragma unroll
            for (int s = 0; s < NIP; s++) {
                pi0[s] = Pip[(w*2 + 0)*4 + s]; mm0 = fmaxf(mm0, pi0[s]);
                pi1[s] = Pip[(w*2 + 1)*4 + s]; mm1 = fmaxf(mm1, pi1[s]);
            }
            float ss0 = 0.f, ss1 = 0.f;
#pragma unroll
            for (int s = 0; s < NIP; s++) {
                pi0[s] = __expf(pi0[s] - mm0); ss0 += pi0[s];
                pi1[s] = __expf(pi1[s] - mm1); ss1 += pi1[s];
            }
            float is0 = 1.f/ss0, is1 = 1.f/ss1;
#pragma unroll
            for (int s = 0; s < NIP; s++) { pi0[s] *= is0; pi1[s] *= is1; }
        }
        if (lane < NIP) {
            Prow0[NKEY + lane] = pi0[lane];
            Prow1[NKEY + lane] = pi1[lane];
        }
        __syncwarp();

        // ---- unified PV over 88 slots (float4 over keys, Vt transposed) ----
        float o0[5] = {0.f,0.f,0.f,0.f,0.f};
        float o1[5] = {0.f,0.f,0.f,0.f,0.f};
#pragma unroll 2
        for (int sb4 = 0; sb4 < 22; sb4++) {
            float4 p0 = *(const float4*)&Prow0[sb4*4];
            float4 p1 = *(const float4*)&Prow1[sb4*4];
#pragma unroll
            for (int i = 0; i < 5; i++) {
                float4 v = *(const float4*)&Vt[(lane + 32*i)*VDIM + sb4*4];
                o0[i] += p0.x*v.x + p0.y*v.y + p0.z*v.z + p0.w*v.w;
                o1[i] += p1.x*v.x + p1.y*v.y + p1.z*v.z + p1.w*v.w;
            }
        }

        const size_t ob0 = ((size_t)b*SEQ + q0)*HS + h*DH;
#pragma unroll
        for (int i = 0; i < 5; i++) {
            int d = lane + 32*i;
            Oh[ob0 +      d] = __float2half_rn(o0[i]);
            Oh[ob0 + HS + d] = __float2half_rn(o1[i]);
        }
        __syncwarp();
    }
}

// ---------------------------------------------------------------------------
// Launch
// ---------------------------------------------------------------------------
extern "C" void kernel_launch(void* const* d_in, const int* in_sizes, int n_in,
                              void* d_out, int out_size)
{
    const float* hs   = (const float*)d_in[0];
    const float* ehs  = (const float*)d_in[1];
    const float* w_q  = (const float*)d_in[2];
    const float* w_k  = (const float*)d_in[3];
    const float* w_v  = (const float*)d_in[4];
    const float* w_ki = (const float*)d_in[5];
    const float* w_vi = (const float*)d_in[6];
    const float* w_o  = (const float*)d_in[7];
    const float* b_o  = (const float*)d_in[8];
    float* out = (float*)d_out;

    float *Qb, *KVq;
    __half *Ah, *Wh, *Eh, *Wq;
    cudaGetSymbolAddress((void**)&Qb,  g_Q);
    cudaGetSymbolAddress((void**)&KVq, g_KVq);
    cudaGetSymbolAddress((void**)&Ah,  g_Ah);
    cudaGetSymbolAddress((void**)&Wh,  g_Wh);
    cudaGetSymbolAddress((void**)&Eh,  g_Eh);
    cudaGetSymbolAddress((void**)&Wq,  g_Wq);

    cudaFuncSetAttribute(attn_k, cudaFuncAttributeMaxDynamicSharedMemorySize, ATT_SMEM);
    cudaFuncSetAttribute(mma_gemm1<HS,false>,     cudaFuncAttributeMaxDynamicSharedMemorySize, MMA_SMEM);
    cudaFuncSetAttribute(mma_gemm1<HS,true>,      cudaFuncAttributeMaxDynamicSharedMemorySize, MMA_SMEM);
    cudaFuncSetAttribute(mma_gemm1<CROSSD,false>, cudaFuncAttributeMaxDynamicSharedMemorySize, MMA_SMEM);

    const int CT = 256;
    dim3 gm(HS/128, MQ/128);   // (10, 256)

    // ---- Q = hidden @ w_q  (fp16 HMMA) ----
    const size_t totA = (size_t)MQ * (HS/4);
    conv_act_h<<<(unsigned)((totA + CT-1)/CT), CT>>>(hs, Ah, totA);
    conv_wt_h<<<dim3(HS/32, HS/32), dim3(32, 8)>>>(w_q, Wh, HS, HS);
    mma_gemm1<HS,false><<<gm, 256, MMA_SMEM>>>(Ah, Wh, nullptr, Qb, HS);

    // ---- quad projection: [K|V|Kip|Vip] = ehs @ [w_k|w_v|w_ki|w_vi] ----
    const size_t totE = (size_t)(BATCH*NCTX) * (CROSSD/4);
    conv_act_h<<<(unsigned)((totE + CT-1)/CT), CT>>>(ehs, Eh, totE);
    dim3 gw(HS/32, CROSSD/32);
    conv_wt_h<<<gw, dim3(32, 8)>>>(w_k,  Wq,                         CROSSD, HS);
    conv_wt_h<<<gw, dim3(32, 8)>>>(w_v,  Wq + (size_t)HS*CROSSD,     CROSSD, HS);
    conv_wt_h<<<gw, dim3(32, 8)>>>(w_ki, Wq + (size_t)2*HS*CROSSD,   CROSSD, HS);
    conv_wt_h<<<gw, dim3(32, 8)>>>(w_vi, Wq + (size_t)3*HS*CROSSD,   CROSSD, HS);
    dim3 gq(NQ/128, MEPAD/128);   // (40, 6)
    mma_gemm1<CROSSD,false><<<gq, 256, MMA_SMEM>>>(Eh, Wq, nullptr, KVq, NQ);

    // ---- out-proj weight conversion (independent; before attention) ----
    conv_wt_h<<<dim3(HS/32, HS/32), dim3(32, 8)>>>(w_o, Wh, HS, HS);

    // ---- fused dual attention -> fp16 activations (overwrites g_Ah) ----
    dim3 ga(SEQ/CHQ, HEADS, BATCH);   // (4, 8, 8)
    attn_k<<<ga, 512, ATT_SMEM>>>(Qb, KVq, Ah);

    // ---- out = attn @ w_out + b  (fp16 HMMA) ----
    mma_gemm1<HS,true><<<gm, 256, MMA_SMEM>>>(Ah, Wh, b_o, out, HS);
}

// round 13
// speedup vs baseline: 4.1581x; 1.0383x over previous
#include <cuda.h>
#include <cuda_runtime.h>
#include <cuda_fp16.h>
#include <math.h>
#include <stdint.h>

// ---------------------------------------------------------------------------
// Problem constants
// ---------------------------------------------------------------------------
#define BATCH   8
#define SEQ     4096
#define HS      1280
#define HEADS   8
#define DH      160
#define NKEY    77
#define NIP     4
#define NCTX    81               // 77 text + 4 ip rows per batch
#define NKALL   81               // all keys resident per (b,h)
#define CROSSD  2048
#define MQ      (BATCH*SEQ)      // 32768
#define NQ      (4*HS)           // 5120  quad projection output columns
#define MEPAD   768              // 648 ctx rows padded to 6 CTA tiles

// Scratch device globals (allocation-free workaround)
__device__ float  g_KVq[MEPAD * NQ];               // quad proj out [K|V|Kip|Vip]
__device__ __half g_Qh[(size_t)MQ * HS];           // fp16 Q projection
__device__ __half g_Ah[(size_t)MQ * HS];           // fp16 activations (hs, then attn out)
__device__ __half g_Wh[(size_t)HS * HS];           // fp16 weight^T (w_q, then w_o)
__device__ __half g_Eh[(size_t)MEPAD * CROSSD];    // fp16 ehs (rows 648+ stay zero)
__device__ __half g_Wq[(size_t)NQ * CROSSD];       // fp16 quad weight^T

// ---------------------------------------------------------------------------
// PTX helpers (portable sm_80+ ISA only)
// ---------------------------------------------------------------------------
__device__ __forceinline__ uint32_t smem_u32(const void* p) {
    uint32_t a;
    asm("{ .reg .u64 t; cvta.to.shared.u64 t, %1; cvt.u32.u64 %0, t; }"
        : "=r"(a) : "l"(p));
    return a;
}

#define CP_ASYNC16(dst, src) \
    asm volatile("cp.async.cg.shared.global [%0], [%1], 16;" \
        :: "r"(dst), "l"(src) : "memory")
#define CP_COMMIT() asm volatile("cp.async.commit_group;" ::: "memory")
#define CP_WAIT(n)  asm volatile("cp.async.wait_group %0;" :: "n"(n) : "memory")

#define LDSM4(r, addr) \
    asm volatile("ldmatrix.sync.aligned.m8n8.x4.shared.b16 {%0,%1,%2,%3}, [%4];" \
        : "=r"((r)[0]), "=r"((r)[1]), "=r"((r)[2]), "=r"((r)[3]) : "r"(addr))

#define MMA16816H(d, a, b0, b1) \
    asm volatile("mma.sync.aligned.m16n8k16.row.col.f32.f16.f16.f32 " \
        "{%0,%1,%2,%3}, {%4,%5,%6,%7}, {%8,%9}, {%0,%1,%2,%3};" \
        : "+f"((d)[0]), "+f"((d)[1]), "+f"((d)[2]), "+f"((d)[3]) \
        : "r"((a)[0]), "r"((a)[1]), "r"((a)[2]), "r"((a)[3]), "r"(b0), "r"(b1))

// ---------------------------------------------------------------------------
// fp16 single-pass tensor-core GEMM:
//   C[M,N] = A_fp16[M,KD] @ B_fp16[N,KD]^T     (fp32 accumulate)
// HALF_OUT selects fp16 vs fp32 output. CTA tile 128x128, K chunk 64
// (128B SW128-swizzled rows), 3-stage cp.async pipeline, 2 CTAs/SM.
// ---------------------------------------------------------------------------
#define KC    64
#define TSTG  16384                 // one 128x64 fp16 tile
#define STG2  (2*TSTG)              // 32768 per stage (A, B)
#define MMA_SMEM (1024 + 3*STG2)    // 99328

template<int KD, bool BIAS, bool HALF_OUT>
__global__ void __launch_bounds__(256, 2)
mma_gemm1(const __half* __restrict__ Ag, const __half* __restrict__ Bg,
          const float* __restrict__ bias, void* __restrict__ Cv, int N)
{
    constexpr int NCH = KD/KC;
    extern __shared__ char dsm[];
    const uint32_t sb = (smem_u32(dsm) + 1023u) & ~1023u;
    const int tid  = threadIdx.x;
    const int lane = tid & 31;
    const int wid  = tid >> 5;
    const int wm   = wid >> 2;        // 0..1  (64-row slab)
    const int wn   = wid & 3;         // 0..3  (32-col slab)
    const int mt   = blockIdx.y, nt = blockIdx.x;

    const __half* Abase = Ag + (size_t)(mt*128) * KD;
    const __half* Bbase = Bg + (size_t)(nt*128) * KD;

    // cp.async loader: per tile, 4 x 16B per thread (1024 chunks / 256 thr)
    int ld_row[4], ld_sw[4], ld_c8[4];
#pragma unroll
    for (int i = 0; i < 4; i++) {
        int idx   = tid + i*256;
        ld_row[i] = idx >> 3;
        int c     = idx & 7;
        ld_c8[i]  = c * 8;
        ld_sw[i]  = (c ^ (ld_row[i] & 7)) << 4;
    }

    auto load_chunk = [&](int ck, int st) {
        const uint32_t s0 = sb + st*STG2;
#pragma unroll
        for (int i = 0; i < 4; i++)
            CP_ASYNC16(s0 + ld_row[i]*128 + ld_sw[i],
                       Abase + (size_t)ld_row[i]*KD + ck*KC + ld_c8[i]);
#pragma unroll
        for (int i = 0; i < 4; i++)
            CP_ASYNC16(s0 + TSTG + ld_row[i]*128 + ld_sw[i],
                       Bbase + (size_t)ld_row[i]*KD + ck*KC + ld_c8[i]);
    };

    float acc[4][4][4];
#pragma unroll
    for (int mi = 0; mi < 4; mi++)
#pragma unroll
        for (int ni = 0; ni < 4; ni++)
#pragma unroll
            for (int j = 0; j < 4; j++) acc[mi][ni][j] = 0.f;

    // ldmatrix lane addressing
    const int a_row  = wm*64 + (lane & 15);                        // + mi*16
    const int b_row  = wn*32 + ((lane >> 3) >> 1)*8 + (lane & 7);  // + p*16
    const int a_coff = lane >> 4;
    const int b_coff = (lane >> 3) & 1;

    // prologue: fill 2 of 3 stages
    load_chunk(0, 0); CP_COMMIT();
    load_chunk(1, 1); CP_COMMIT();

    int st = 0, pst = 2;
    for (int ck = 0; ck < NCH; ck++) {
        CP_WAIT(1);
        __syncthreads();

        if (ck + 2 < NCH) load_chunk(ck + 2, pst);
        CP_COMMIT();

        const uint32_t a_s = sb + st*STG2;
        const uint32_t b_s = a_s + TSTG;

#pragma unroll
        for (int ks = 0; ks < 4; ks++) {
            uint32_t ah[4][4], bh[2][4];
#pragma unroll
            for (int mi = 0; mi < 4; mi++) {
                int row = a_row + mi*16;
                int c   = ks*2 + a_coff;
                LDSM4(ah[mi], a_s + row*128 + ((c ^ (row & 7)) << 4));
            }
#pragma unroll
            for (int p = 0; p < 2; p++) {
                int row = b_row + p*16;
                int c   = ks*2 + b_coff;
                LDSM4(bh[p], b_s + row*128 + ((c ^ (row & 7)) << 4));
            }
#pragma unroll
            for (int mi = 0; mi < 4; mi++)
#pragma unroll
                for (int ni = 0; ni < 4; ni++) {
                    const int q = ni >> 1, r = (ni & 1)*2;
                    MMA16816H(acc[mi][ni], ah[mi], bh[q][r], bh[q][r+1]);
                }
        }
        __syncthreads();
        st  = (st  + 1 == 3) ? 0 : st  + 1;
        pst = (pst + 1 == 3) ? 0 : pst + 1;
    }

    // epilogue: registers -> gmem (fp32 or fp16)
    const int g = lane >> 2, tq = lane & 3;
#pragma unroll
    for (int mi = 0; mi < 4; mi++) {
#pragma unroll
        for (int ni = 0; ni < 4; ni++) {
            int row0 = mt*128 + wm*64 + mi*16 + g;
            int col  = nt*128 + wn*32 + ni*8 + tq*2;
            float bx = 0.f, by = 0.f;
            if (BIAS) { bx = bias[col]; by = bias[col+1]; }
            float v00 = acc[mi][ni][0] + bx, v01 = acc[mi][ni][1] + by;
            float v10 = acc[mi][ni][2] + bx, v11 = acc[mi][ni][3] + by;
            if (HALF_OUT) {
                __half* C = (__half*)Cv;
                *(__half2*)(C + (size_t)row0 * N + col)     = __floats2half2_rn(v00, v01);
                *(__half2*)(C + (size_t)(row0+8) * N + col) = __floats2half2_rn(v10, v11);
            } else {
                float* C = (float*)Cv;
                *(float2*)(C + (size_t)row0 * N + col)     = make_float2(v00, v01);
                *(float2*)(C + (size_t)(row0+8) * N + col) = make_float2(v10, v11);
            }
        }
    }
}

// ---------------------------------------------------------------------------
// fp32 -> fp16 conversions
// ---------------------------------------------------------------------------
__global__ void conv_act_h(const float* __restrict__ X, __half* __restrict__ Y,
                           size_t tot4)
{
    size_t i = (size_t)blockIdx.x * blockDim.x + threadIdx.x;
    if (i >= tot4) return;
    float4 v = reinterpret_cast<const float4*>(X)[i];
    __half2* p = (__half2*)(Y + i*4);
    p[0] = __floats2half2_rn(v.x, v.y);
    p[1] = __floats2half2_rn(v.z, v.w);
}

// weights: W[K,N] f32 -> Y[N,K] fp16 transposed
__global__ void conv_wt_h(const float* __restrict__ W, __half* __restrict__ Y,
                          int K, int N)
{
    __shared__ float t[32][33];
    int n0 = blockIdx.x * 32, k0 = blockIdx.y * 32;
    int tx = threadIdx.x, ty = threadIdx.y;
#pragma unroll
    for (int j = 0; j < 32; j += 8)
        t[ty+j][tx] = W[(size_t)(k0+ty+j) * N + n0 + tx];
    __syncthreads();
#pragma unroll
    for (int j = 0; j < 32; j += 8) {
        int n = n0 + ty + j, k = k0 + tx;
        Y[(size_t)n * K + k] = __float2half_rn(t[tx][ty+j]);
    }
}

// merged quad weight conversion: blockIdx.z selects among 4 weights
__global__ void conv_wt_h4(const float* __restrict__ W0, const float* __restrict__ W1,
                           const float* __restrict__ W2, const float* __restrict__ W3,
                           __half* __restrict__ Y, int K, int N)
{
    __shared__ float t[32][33];
    const float* W = (blockIdx.z == 0) ? W0 : (blockIdx.z == 1) ? W1
                   : (blockIdx.z == 2) ? W2 : W3;
    __half* Yp = Y + (size_t)blockIdx.z * N * K;
    int n0 = blockIdx.x * 32, k0 = blockIdx.y * 32;
    int tx = threadIdx.x, ty = threadIdx.y;
#pragma unroll
    for (int j = 0; j < 32; j += 8)
        t[ty+j][tx] = W[(size_t)(k0+ty+j) * N + n0 + tx];
    __syncthreads();
#pragma unroll
    for (int j = 0; j < 32; j += 8) {
        int n = n0 + ty + j, k = k0 + tx;
        Yp[(size_t)n * K + k] = __float2half_rn(t[tx][ty+j]);
    }
}

// ---------------------------------------------------------------------------
// Fused dual attention, vectorized; Q in fp16; balanced grid (1024 CTAs).
// ---------------------------------------------------------------------------
#define CHQ      256
#define AT_WARPS 16
#define SDIM     164
#define VDIM     92

#define ATT_SMEM ((NKALL*SDIM + DH*VDIM + 2*AT_WARPS*VDIM + 2*AT_WARPS*4) * 4)

__global__ void __launch_bounds__(512, 1)
attn_k(const __half* __restrict__ Q, const float* __restrict__ KVq,
       __half* __restrict__ Oh)
{
    extern __shared__ float sm[];
    float* Ks  = sm;                        // 81 x 164
    float* Vt  = Ks + NKALL*SDIM;           // 160 x 92
    float* Ps  = Vt + DH*VDIM;              // 32 x 92
    float* Pip = Ps + 2*AT_WARPS*VDIM;      // 32 x 4

    const int b    = blockIdx.z;
    const int h    = blockIdx.y;
    const int ch   = blockIdx.x;
    const int tid  = threadIdx.x;
    const int w    = tid >> 5;
    const int lane = tid & 31;

    for (int idx = tid; idx < DH*11; idx += 512) {
        int d = idx / 11, s = 81 + idx % 11;
        Vt[d*VDIM + s] = 0.f;
    }
    for (int idx = tid; idx < NKALL*DH; idx += 512) {
        int s = idx / DH, d = idx % DH;
        size_t src = (size_t)(b*NCTX + s)*NQ + h*DH + d;
        float kv = (s < NKEY) ? KVq[src]      : KVq[src + 2*HS];
        float vv = (s < NKEY) ? KVq[src + HS] : KVq[src + 3*HS];
        Ks[s*SDIM + d] = kv;
        Vt[d*VDIM + s] = vv;
    }
    __syncthreads();

    const float scale = 0.07905694150420949f;  // 1/sqrt(160)

    int  krow[3]; bool kval[3];
#pragma unroll
    for (int j = 0; j < 3; j++) {
        int s   = lane + 32*j;
        kval[j] = (s < NKEY);
        krow[j] = (kval[j] ? s : 0) * SDIM;
    }
    const int iprow = (NKEY + (lane & 3)) * SDIM;

    float* Prow0 = Ps + (w*2 + 0)*VDIM;
    float* Prow1 = Ps + (w*2 + 1)*VDIM;

    for (int qp = w; qp < CHQ/2; qp += AT_WARPS) {
        const int    q0 = ch*CHQ + qp*2;
        const size_t r0 = ((size_t)b*SEQ + q0)*HS + h*DH;

        float qv0[5], qv1[5];
#pragma unroll
        for (int i = 0; i < 5; i++) {
            qv0[i] = __half2float(Q[r0 +      lane + 32*i]);
            qv1[i] = __half2float(Q[r0 + HS + lane + 32*i]);
        }

        float sc0[3] = {0.f,0.f,0.f}, sc1[3] = {0.f,0.f,0.f};
        float si0 = 0.f, si1 = 0.f;
#pragma unroll
        for (int i = 0; i < 5; i++) {
            float a0 = qv0[i], a1 = qv1[i];
#pragma unroll
            for (int d4 = 0; d4 < 8; d4++) {
                const int doff = i*32 + d4*4;
                float4 k0 = *(const float4*)&Ks[krow[0] + doff];
                float4 k1 = *(const float4*)&Ks[krow[1] + doff];
                float4 k2 = *(const float4*)&Ks[krow[2] + doff];
                float4 ki = *(const float4*)&Ks[iprow   + doff];
#pragma unroll
                for (int c = 0; c < 4; c++) {
                    float q0v = __shfl_sync(0xffffffffu, a0, d4*4 + c);
                    float q1v = __shfl_sync(0xffffffffu, a1, d4*4 + c);
                    float kk0 = (&k0.x)[c], kk1 = (&k1.x)[c];
                    float kk2 = (&k2.x)[c], kki = (&ki.x)[c];
                    sc0[0] += q0v*kk0; sc0[1] += q0v*kk1; sc0[2] += q0v*kk2;
                    si0    += q0v*kki;
                    sc1[0] += q1v*kk0; sc1[1] += q1v*kk1; sc1[2] += q1v*kk2;
                    si1    += q1v*kki;
                }
            }
        }

        // ---- text softmax (warp-wide over 77 keys) ----
        float m0 = -1e30f, m1 = -1e30f;
#pragma unroll
        for (int j = 0; j < 3; j++) {
            sc0[j] = kval[j] ? sc0[j]*scale : -1e30f;
            sc1[j] = kval[j] ? sc1[j]*scale : -1e30f;
            m0 = fmaxf(m0, sc0[j]);
            m1 = fmaxf(m1, sc1[j]);
        }
#pragma unroll
        for (int off = 16; off >= 1; off >>= 1) {
            m0 = fmaxf(m0, __shfl_xor_sync(0xffffffffu, m0, off));
            m1 = fmaxf(m1, __shfl_xor_sync(0xffffffffu, m1, off));
        }
        float e0[3], e1[3], s0 = 0.f, s1 = 0.f;
#pragma unroll
        for (int j = 0; j < 3; j++) {
            e0[j] = __expf(sc0[j] - m0); s0 += e0[j];
            e1[j] = __expf(sc1[j] - m1); s1 += e1[j];
        }
#pragma unroll
        for (int off = 16; off >= 1; off >>= 1) {
            s0 += __shfl_xor_sync(0xffffffffu, s0, off);
            s1 += __shfl_xor_sync(0xffffffffu, s1, off);
        }
        const float inv0 = 1.f / s0, inv1 = 1.f / s1;

        __syncwarp();
#pragma unroll
        for (int j = 0; j < 3; j++) {
            int s = lane + 32*j;
            if (s < 88) {
                Prow0[s] = e0[j] * inv0;
                Prow1[s] = e1[j] * inv1;
            }
        }
        if (lane < NIP) {
            Pip[(w*2 + 0)*4 + lane] = si0 * scale;
            Pip[(w*2 + 1)*4 + lane] = si1 * scale;
        }
        __syncwarp();

        // ---- ip softmax (4 keys, redundant per lane) ----
        float pi0[NIP], pi1[NIP];
        {
            float mm0 = -1e30f, mm1 = -1e30f;
#pragma unroll
            for (int s = 0; s < NIP; s++) {
                pi0[s] = Pip[(w*2 + 0)*4 + s]; mm0 = fmaxf(mm0, pi0[s]);
                pi1[s] = Pip[(w*2 + 1)*4 + s]; mm1 = fmaxf(mm1, pi1[s]);
            }
            float ss0 = 0.f, ss1 = 0.f;
#pragma unroll
            for (int s = 0; s < NIP; s++) {
                pi0[s] = __expf(pi0[s] - mm0); ss0 += pi0[s];
                pi1[s] = __expf(pi1[s] - mm1); ss1 += pi1[s];
            }
            float is0 = 1.f/ss0, is1 = 1.f/ss1;
#pragma unroll
            for (int s = 0; s < NIP; s++) { pi0[s] *= is0; pi1[s] *= is1; }
        }
        if (lane < NIP) {
            Prow0[NKEY + lane] = pi0[lane];
            Prow1[NKEY + lane] = pi1[lane];
        }
        __syncwarp();

        // ---- unified PV over 88 slots (float4 over keys, Vt transposed) ----
        float o0[5] = {0.f,0.f,0.f,0.f,0.f};
        float o1[5] = {0.f,0.f,0.f,0.f,0.f};
#pragma unroll 2
        for (int sb4 = 0; sb4 < 22; sb4++) {
            float4 p0 = *(const float4*)&Prow0[sb4*4];
            float4 p1 = *(const float4*)&Prow1[sb4*4];
#pragma unroll
            for (int i = 0; i < 5; i++) {
                float4 v = *(const float4*)&Vt[(lane + 32*i)*VDIM + sb4*4];
                o0[i] += p0.x*v.x + p0.y*v.y + p0.z*v.z + p0.w*v.w;
                o1[i] += p1.x*v.x + p1.y*v.y + p1.z*v.z + p1.w*v.w;
            }
        }

        const size_t ob0 = ((size_t)b*SEQ + q0)*HS + h*DH;
#pragma unroll
        for (int i = 0; i < 5; i++) {
            int d = lane + 32*i;
            Oh[ob0 +      d] = __float2half_rn(o0[i]);
            Oh[ob0 + HS + d] = __float2half_rn(o1[i]);
        }
        __syncwarp();
    }
}

// ---------------------------------------------------------------------------
// Launch
// ---------------------------------------------------------------------------
extern "C" void kernel_launch(void* const* d_in, const int* in_sizes, int n_in,
                              void* d_out, int out_size)
{
    const float* hs   = (const float*)d_in[0];
    const float* ehs  = (const float*)d_in[1];
    const float* w_q  = (const float*)d_in[2];
    const float* w_k  = (const float*)d_in[3];
    const float* w_v  = (const float*)d_in[4];
    const float* w_ki = (const float*)d_in[5];
    const float* w_vi = (const float*)d_in[6];
    const float* w_o  = (const float*)d_in[7];
    const float* b_o  = (const float*)d_in[8];
    float* out = (float*)d_out;

    float *KVq;
    __half *Qh, *Ah, *Wh, *Eh, *Wq;
    cudaGetSymbolAddress((void**)&KVq, g_KVq);
    cudaGetSymbolAddress((void**)&Qh,  g_Qh);
    cudaGetSymbolAddress((void**)&Ah,  g_Ah);
    cudaGetSymbolAddress((void**)&Wh,  g_Wh);
    cudaGetSymbolAddress((void**)&Eh,  g_Eh);
    cudaGetSymbolAddress((void**)&Wq,  g_Wq);

    cudaFuncSetAttribute(attn_k, cudaFuncAttributeMaxDynamicSharedMemorySize, ATT_SMEM);
    cudaFuncSetAttribute(mma_gemm1<HS,false,true>,      cudaFuncAttributeMaxDynamicSharedMemorySize, MMA_SMEM);
    cudaFuncSetAttribute(mma_gemm1<HS,true,false>,      cudaFuncAttributeMaxDynamicSharedMemorySize, MMA_SMEM);
    cudaFuncSetAttribute(mma_gemm1<CROSSD,false,false>, cudaFuncAttributeMaxDynamicSharedMemorySize, MMA_SMEM);

    const int CT = 256;
    dim3 gm(HS/128, MQ/128);   // (10, 256)

    // ---- Q = hidden @ w_q  (fp16 HMMA, fp16 output) ----
    const size_t totA = (size_t)MQ * (HS/4);
    conv_act_h<<<(unsigned)((totA + CT-1)/CT), CT>>>(hs, Ah, totA);
    conv_wt_h<<<dim3(HS/32, HS/32), dim3(32, 8)>>>(w_q, Wh, HS, HS);
    mma_gemm1<HS,false,true><<<gm, 256, MMA_SMEM>>>(Ah, Wh, nullptr, Qh, HS);

    // ---- quad projection: [K|V|Kip|Vip] = ehs @ [w_k|w_v|w_ki|w_vi] ----
    const size_t totE = (size_t)(BATCH*NCTX) * (CROSSD/4);
    conv_act_h<<<(unsigned)((totE + CT-1)/CT), CT>>>(ehs, Eh, totE);
    conv_wt_h4<<<dim3(HS/32, CROSSD/32, 4), dim3(32, 8)>>>(w_k, w_v, w_ki, w_vi,
                                                           Wq, CROSSD, HS);
    dim3 gq(NQ/128, MEPAD/128);   // (40, 6)
    mma_gemm1<CROSSD,false,false><<<gq, 256, MMA_SMEM>>>(Eh, Wq, nullptr, KVq, NQ);

    // ---- out-proj weight conversion (independent; before attention) ----
    conv_wt_h<<<dim3(HS/32, HS/32), dim3(32, 8)>>>(w_o, Wh, HS, HS);

    // ---- fused dual attention -> fp16 activations (overwrites g_Ah) ----
    dim3 ga(SEQ/CHQ, HEADS, BATCH);   // (16, 8, 8) = 1024 CTAs
    attn_k<<<ga, 512, ATT_SMEM>>>(Qh, KVq, Ah);

    // ---- out = attn @ w_out + b  (fp16 HMMA, fp32 output) ----
    mma_gemm1<HS,true,false><<<gm, 256, MMA_SMEM>>>(Ah, Wh, b_o, out, HS);
}

// round 16
// speedup vs baseline: 6.8697x; 1.6521x over previous
#include <cuda.h>
#include <cuda_runtime.h>
#include <cuda_fp16.h>
#include <math.h>
#include <stdint.h>

// ---------------------------------------------------------------------------
// Problem constants
// ---------------------------------------------------------------------------
#define BATCH   8
#define SEQ     4096
#define HS      1280
#define HEADS   8
#define DH      160
#define NKEY    77
#define NIP     4
#define NCTX    81
#define CROSSD  2048
#define MQ      (BATCH*SEQ)      // 32768
#define NQ      (4*HS)           // 5120
#define MEPAD   768
#define NKP     96               // keys padded (77 text + 4 ip + 15 pad)

// Scratch device globals
__device__ __half g_KVq[(size_t)MEPAD * NQ];       // quad proj out fp16 [K|V|Kip|Vip]
__device__ __half g_Qh[(size_t)MQ * HS];           // fp16 Q projection
__device__ __half g_Ah[(size_t)MQ * HS];           // fp16 activations (hs, then attn out)
__device__ __half g_Wh[(size_t)HS * HS];           // fp16 weight^T (w_q, then w_o)
__device__ __half g_Eh[(size_t)MEPAD * CROSSD];    // fp16 ehs (pad rows stay zero)
__device__ __half g_Wq[(size_t)NQ * CROSSD];       // fp16 quad weight^T
__device__ __half g_Vt[(size_t)BATCH*HEADS*DH*NKP];// V transposed per (b,h): [d][key]

// ---------------------------------------------------------------------------
// PTX helpers (portable sm_80+ ISA only)
// ---------------------------------------------------------------------------
__device__ __forceinline__ uint32_t smem_u32(const void* p) {
    uint32_t a;
    asm("{ .reg .u64 t; cvta.to.shared.u64 t, %1; cvt.u32.u64 %0, t; }"
        : "=r"(a) : "l"(p));
    return a;
}

#define CP_ASYNC16(dst, src) \
    asm volatile("cp.async.cg.shared.global [%0], [%1], 16;" \
        :: "r"(dst), "l"(src) : "memory")
#define CP_COMMIT() asm volatile("cp.async.commit_group;" ::: "memory")
#define CP_WAIT(n)  asm volatile("cp.async.wait_group %0;" :: "n"(n) : "memory")

#define LDSM4(r, addr) \
    asm volatile("ldmatrix.sync.aligned.m8n8.x4.shared.b16 {%0,%1,%2,%3}, [%4];" \
        : "=r"((r)[0]), "=r"((r)[1]), "=r"((r)[2]), "=r"((r)[3]) : "r"(addr))

#define MMA16816H(d, a, b0, b1) \
    asm volatile("mma.sync.aligned.m16n8k16.row.col.f32.f16.f16.f32 " \
        "{%0,%1,%2,%3}, {%4,%5,%6,%7}, {%8,%9}, {%0,%1,%2,%3};" \
        : "+f"((d)[0]), "+f"((d)[1]), "+f"((d)[2]), "+f"((d)[3]) \
        : "r"((a)[0]), "r"((a)[1]), "r"((a)[2]), "r"((a)[3]), "r"(b0), "r"(b1))

// 16B-chunk xor swizzle within 8-chunk groups.
// REQUIRES row stride to be a multiple of 8 chunks (128 bytes).
__device__ __forceinline__ int swz(int kc, int r) {
    return ((kc ^ r) & 7) | (kc & ~7);
}

// ---------------------------------------------------------------------------
// fp16 single-pass tensor-core GEMM (unchanged, proven)
// ---------------------------------------------------------------------------
#define KC    64
#define TSTG  16384
#define STG2  (2*TSTG)
#define MMA_SMEM (1024 + 3*STG2)

template<int KD, bool BIAS, bool HALF_OUT>
__global__ void __launch_bounds__(256, 2)
mma_gemm1(const __half* __restrict__ Ag, const __half* __restrict__ Bg,
          const float* __restrict__ bias, void* __restrict__ Cv, int N)
{
    constexpr int NCH = KD/KC;
    extern __shared__ char dsm[];
    const uint32_t sb = (smem_u32(dsm) + 1023u) & ~1023u;
    const int tid  = threadIdx.x;
    const int lane = tid & 31;
    const int wid  = tid >> 5;
    const int wm   = wid >> 2;
    const int wn   = wid & 3;
    const int mt   = blockIdx.y, nt = blockIdx.x;

    const __half* Abase = Ag + (size_t)(mt*128) * KD;
    const __half* Bbase = Bg + (size_t)(nt*128) * KD;

    int ld_row[4], ld_sw[4], ld_c8[4];
#pragma unroll
    for (int i = 0; i < 4; i++) {
        int idx   = tid + i*256;
        ld_row[i] = idx >> 3;
        int c     = idx & 7;
        ld_c8[i]  = c * 8;
        ld_sw[i]  = (c ^ (ld_row[i] & 7)) << 4;
    }

    auto load_chunk = [&](int ck, int st) {
        const uint32_t s0 = sb + st*STG2;
#pragma unroll
        for (int i = 0; i < 4; i++)
            CP_ASYNC16(s0 + ld_row[i]*128 + ld_sw[i],
                       Abase + (size_t)ld_row[i]*KD + ck*KC + ld_c8[i]);
#pragma unroll
        for (int i = 0; i < 4; i++)
            CP_ASYNC16(s0 + TSTG + ld_row[i]*128 + ld_sw[i],
                       Bbase + (size_t)ld_row[i]*KD + ck*KC + ld_c8[i]);
    };

    float acc[4][4][4];
#pragma unroll
    for (int mi = 0; mi < 4; mi++)
#pragma unroll
        for (int ni = 0; ni < 4; ni++)
#pragma unroll
            for (int j = 0; j < 4; j++) acc[mi][ni][j] = 0.f;

    const int a_row  = wm*64 + (lane & 15);
    const int b_row  = wn*32 + ((lane >> 3) >> 1)*8 + (lane & 7);
    const int a_coff = lane >> 4;
    const int b_coff = (lane >> 3) & 1;

    load_chunk(0, 0); CP_COMMIT();
    load_chunk(1, 1); CP_COMMIT();

    int st = 0, pst = 2;
    for (int ck = 0; ck < NCH; ck++) {
        CP_WAIT(1);
        __syncthreads();

        if (ck + 2 < NCH) load_chunk(ck + 2, pst);
        CP_COMMIT();

        const uint32_t a_s = sb + st*STG2;
        const uint32_t b_s = a_s + TSTG;

#pragma unroll
        for (int ks = 0; ks < 4; ks++) {
            uint32_t ah[4][4], bh[2][4];
#pragma unroll
            for (int mi = 0; mi < 4; mi++) {
                int row = a_row + mi*16;
                int c   = ks*2 + a_coff;
                LDSM4(ah[mi], a_s + row*128 + ((c ^ (row & 7)) << 4));
            }
#pragma unroll
            for (int p = 0; p < 2; p++) {
                int row = b_row + p*16;
                int c   = ks*2 + b_coff;
                LDSM4(bh[p], b_s + row*128 + ((c ^ (row & 7)) << 4));
            }
#pragma unroll
            for (int mi = 0; mi < 4; mi++)
#pragma unroll
                for (int ni = 0; ni < 4; ni++) {
                    const int q = ni >> 1, r = (ni & 1)*2;
                    MMA16816H(acc[mi][ni], ah[mi], bh[q][r], bh[q][r+1]);
                }
        }
        __syncthreads();
        st  = (st  + 1 == 3) ? 0 : st  + 1;
        pst = (pst + 1 == 3) ? 0 : pst + 1;
    }

    const int g = lane >> 2, tq = lane & 3;
#pragma unroll
    for (int mi = 0; mi < 4; mi++) {
#pragma unroll
        for (int ni = 0; ni < 4; ni++) {
            int row0 = mt*128 + wm*64 + mi*16 + g;
            int col  = nt*128 + wn*32 + ni*8 + tq*2;
            float bx = 0.f, by = 0.f;
            if (BIAS) { bx = bias[col]; by = bias[col+1]; }
            float v00 = acc[mi][ni][0] + bx, v01 = acc[mi][ni][1] + by;
            float v10 = acc[mi][ni][2] + bx, v11 = acc[mi][ni][3] + by;
            if (HALF_OUT) {
                __half* C = (__half*)Cv;
                *(__half2*)(C + (size_t)row0 * N + col)     = __floats2half2_rn(v00, v01);
                *(__half2*)(C + (size_t)(row0+8) * N + col) = __floats2half2_rn(v10, v11);
            } else {
                float* C = (float*)Cv;
                *(float2*)(C + (size_t)row0 * N + col)     = make_float2(v00, v01);
                *(float2*)(C + (size_t)(row0+8) * N + col) = make_float2(v10, v11);
            }
        }
    }
}

// ---------------------------------------------------------------------------
// fp32 -> fp16 conversions
// ---------------------------------------------------------------------------
__global__ void conv_act_h(const float* __restrict__ X, __half* __restrict__ Y,
                           size_t tot4)
{
    size_t i = (size_t)blockIdx.x * blockDim.x + threadIdx.x;
    if (i >= tot4) return;
    float4 v = reinterpret_cast<const float4*>(X)[i];
    __half2* p = (__half2*)(Y + i*4);
    p[0] = __floats2half2_rn(v.x, v.y);
    p[1] = __floats2half2_rn(v.z, v.w);
}

__global__ void conv_wt_h(const float* __restrict__ W, __half* __restrict__ Y,
                          int K, int N)
{
    __shared__ float t[32][33];
    int n0 = blockIdx.x * 32, k0 = blockIdx.y * 32;
    int tx = threadIdx.x, ty = threadIdx.y;
#pragma unroll
    for (int j = 0; j < 32; j += 8)
        t[ty+j][tx] = W[(size_t)(k0+ty+j) * N + n0 + tx];
    __syncthreads();
#pragma unroll
    for (int j = 0; j < 32; j += 8) {
        int n = n0 + ty + j, k = k0 + tx;
        Y[(size_t)n * K + k] = __float2half_rn(t[tx][ty+j]);
    }
}

__global__ void conv_wt_h4(const float* __restrict__ W0, const float* __restrict__ W1,
                           const float* __restrict__ W2, const float* __restrict__ W3,
                           __half* __restrict__ Y, int K, int N)
{
    __shared__ float t[32][33];
    const float* W = (blockIdx.z == 0) ? W0 : (blockIdx.z == 1) ? W1
                   : (blockIdx.z == 2) ? W2 : W3;
    __half* Yp = Y + (size_t)blockIdx.z * N * K;
    int n0 = blockIdx.x * 32, k0 = blockIdx.y * 32;
    int tx = threadIdx.x, ty = threadIdx.y;
#pragma unroll
    for (int j = 0; j < 32; j += 8)
        t[ty+j][tx] = W[(size_t)(k0+ty+j) * N + n0 + tx];
    __syncthreads();
#pragma unroll
    for (int j = 0; j < 32; j += 8) {
        int n = n0 + ty + j, k = k0 + tx;
        Yp[(size_t)n * K + k] = __float2half_rn(t[tx][ty+j]);
    }
}

// ---------------------------------------------------------------------------
// V transpose: KVq -> g_Vt[(b,h)][d][key], keys padded to 96 (pad = 0)
// ---------------------------------------------------------------------------
__global__ void transp_v(const __half* __restrict__ KV, __half* __restrict__ Vt)
{
    int bh = blockIdx.x;
    int b = bh >> 3, h = bh & 7;
    __half* out = Vt + (size_t)bh * DH * NKP;
    for (int idx = threadIdx.x; idx < DH*NKP; idx += 256) {
        int d = idx / NKP, s = idx % NKP;
        __half v = __float2half(0.f);
        if (s < NKEY)
            v = KV[(size_t)(b*NCTX + s)*NQ + HS + h*DH + d];
        else if (s < NCTX)
            v = KV[(size_t)(b*NCTX + s)*NQ + 3*HS + h*DH + d];
        out[(size_t)d * NKP + s] = v;
    }
}

// ---------------------------------------------------------------------------
// Tensor-core fused dual attention.
// CTA = (128 queries, head, batch); 8 warps x 16 queries.
// smem: Qs[128][160h, 384B stride] | Ks[96][160h, 384B]
//       | Vs[160][96h, 256B stride] | P[8 warps][16][96h, 256B stride]
// Strides are multiples of 128B so the xor swizzle stays in-row (round-15
// bug: 192B stride made chunks 8-11 swizzle past the row end).
// ---------------------------------------------------------------------------
#define QSTR  384
#define VSTR  256
#define KOFF  (128*QSTR)               // 49152
#define VOFF  (KOFF + NKP*QSTR)        // 86016
#define POFF  (VOFF + DH*VSTR)         // 126976
#define PWSZ  (16*VSTR)                // 4096 per warp
#define ATT_SMEM (POFF + 8*PWSZ + 256) // 160000

__global__ void __launch_bounds__(256, 1)
attn_mma(const __half* __restrict__ Q, const __half* __restrict__ KV,
         const __half* __restrict__ Vt, __half* __restrict__ Oh)
{
    extern __shared__ char dsm[];
    const uint32_t sb = (smem_u32(dsm) + 127u) & ~127u;
    char* smb = dsm + ((128 - ((uintptr_t)dsm & 127)) & 127);

    const int b = blockIdx.z, h = blockIdx.y, ch = blockIdx.x;
    const int tid = threadIdx.x, w = tid >> 5, lane = tid & 31;

    // ---- cooperative loads (uint4 = 8 half) ----
    const __half* Qg = Q + ((size_t)(b*SEQ + ch*128))*HS + h*DH;
    for (int idx = tid; idx < 128*20; idx += 256) {
        int row = idx / 20, kc = idx % 20;
        *(uint4*)(smb + row*QSTR + swz(kc,row)*16) =
            *(const uint4*)(Qg + (size_t)row*HS + kc*8);
    }
    for (int idx = tid; idx < NCTX*20; idx += 256) {
        int s = idx / 20, kc = idx % 20;
        size_t off = (s < NKEY) ? 0 : (size_t)2*HS;
        *(uint4*)(smb + KOFF + s*QSTR + swz(kc,s)*16) =
            *(const uint4*)(KV + (size_t)(b*NCTX + s)*NQ + h*DH + off + kc*8);
    }
    const __half* Vg = Vt + (size_t)(b*HEADS + h)*DH*NKP;
    for (int idx = tid; idx < DH*12; idx += 256) {
        int row = idx / 12, kc = idx % 12;
        *(uint4*)(smb + VOFF + row*VSTR + swz(kc,row)*16) =
            *(const uint4*)(Vg + (size_t)row*NKP + kc*8);
    }
    __syncthreads();

    // ---- S = Q K^T : warp tile 16q x 96k ----
    float sacc[12][4];
#pragma unroll
    for (int nt = 0; nt < 12; nt++)
#pragma unroll
        for (int j = 0; j < 4; j++) sacc[nt][j] = 0.f;

    const int aq_row = w*16 + (lane & 15);
    const int bk_sub = ((lane >> 3) >> 1)*8 + (lane & 7);
    const int a_coff = lane >> 4;
    const int b_coff = (lane >> 3) & 1;

#pragma unroll
    for (int ks = 0; ks < 10; ks++) {
        uint32_t aq[4];
        LDSM4(aq, sb + aq_row*QSTR + swz(ks*2 + a_coff, aq_row)*16);
        uint32_t bk[6][4];
#pragma unroll
        for (int nb = 0; nb < 6; nb++) {
            int row = nb*16 + bk_sub;
            LDSM4(bk[nb], sb + KOFF + row*QSTR + swz(ks*2 + b_coff, row)*16);
        }
#pragma unroll
        for (int nt = 0; nt < 12; nt++)
            MMA16816H(sacc[nt], aq, bk[nt>>1][(nt&1)*2], bk[nt>>1][(nt&1)*2+1]);
    }

    // ---- dual masked softmax on acc layout ----
    const float scale = 0.07905694150420949f;  // 1/sqrt(160)
    const int g = lane >> 2, cbase = (lane & 3)*2;

    float mt[2] = {-1e30f, -1e30f}, mi[2] = {-1e30f, -1e30f};
#pragma unroll
    for (int nt = 0; nt < 12; nt++)
#pragma unroll
        for (int r = 0; r < 2; r++)
#pragma unroll
            for (int j = 0; j < 2; j++) {
                int col = nt*8 + cbase + j;
                float v = sacc[nt][r*2+j] * scale;
                if (col >= NCTX) v = -1e30f;
                sacc[nt][r*2+j] = v;
                if (col < NKEY) mt[r] = fmaxf(mt[r], v);
                else            mi[r] = fmaxf(mi[r], v);
            }
#pragma unroll
    for (int off = 1; off <= 2; off <<= 1) {
#pragma unroll
        for (int r = 0; r < 2; r++) {
            mt[r] = fmaxf(mt[r], __shfl_xor_sync(0xffffffffu, mt[r], off));
            mi[r] = fmaxf(mi[r], __shfl_xor_sync(0xffffffffu, mi[r], off));
        }
    }
    float st[2] = {0.f, 0.f}, si[2] = {0.f, 0.f};
#pragma unroll
    for (int nt = 0; nt < 12; nt++)
#pragma unroll
        for (int r = 0; r < 2; r++)
#pragma unroll
            for (int j = 0; j < 2; j++) {
                int col = nt*8 + cbase + j;
                float v = sacc[nt][r*2+j], e;
                if (col < NKEY) { e = __expf(v - mt[r]); st[r] += e; }
                else            { e = __expf(v - mi[r]); si[r] += e; }
                sacc[nt][r*2+j] = e;
            }
#pragma unroll
    for (int off = 1; off <= 2; off <<= 1) {
#pragma unroll
        for (int r = 0; r < 2; r++) {
            st[r] += __shfl_xor_sync(0xffffffffu, st[r], off);
            si[r] += __shfl_xor_sync(0xffffffffu, si[r], off);
        }
    }
    float it[2] = {1.f/st[0], 1.f/st[1]}, ii[2] = {1.f/si[0], 1.f/si[1]};

    // ---- store P fp16 to per-warp smem ----
    const uint32_t pw = sb + POFF + w*PWSZ;
#pragma unroll
    for (int nt = 0; nt < 12; nt++)
#pragma unroll
        for (int r = 0; r < 2; r++) {
            int col = nt*8 + cbase;
            float p0 = sacc[nt][r*2+0] * ((col   < NKEY) ? it[r] : ii[r]);
            float p1 = sacc[nt][r*2+1] * ((col+1 < NKEY) ? it[r] : ii[r]);
            int row = g + r*8;
            *(__half2*)(smb + POFF + w*PWSZ + row*VSTR + swz(nt,row)*16 + (lane&3)*4)
                = __floats2half2_rn(p0, p1);
        }
    __syncwarp();

    // ---- O = P Vt : warp tile 16q x 160d ----
    float oacc[20][4];
#pragma unroll
    for (int nt = 0; nt < 20; nt++)
#pragma unroll
        for (int j = 0; j < 4; j++) oacc[nt][j] = 0.f;

#pragma unroll
    for (int kt = 0; kt < 6; kt++) {
        uint32_t ap[4];
        int prow = lane & 15;
        LDSM4(ap, pw + prow*VSTR + swz(kt*2 + a_coff, prow)*16);
        uint32_t bv[10][4];
#pragma unroll
        for (int nb = 0; nb < 10; nb++) {
            int row = nb*16 + bk_sub;
            LDSM4(bv[nb], sb + VOFF + row*VSTR + swz(kt*2 + b_coff, row)*16);
        }
#pragma unroll
        for (int nt = 0; nt < 20; nt++)
            MMA16816H(oacc[nt], ap, bv[nt>>1][(nt&1)*2], bv[nt>>1][(nt&1)*2+1]);
    }

    // ---- store O fp16 ----
    const size_t obase = ((size_t)(b*SEQ + ch*128 + w*16))*HS + h*DH;
#pragma unroll
    for (int nt = 0; nt < 20; nt++) {
        int col = nt*8 + cbase;
        *(__half2*)(Oh + obase + (size_t)g*HS + col)
            = __floats2half2_rn(oacc[nt][0], oacc[nt][1]);
        *(__half2*)(Oh + obase + (size_t)(g+8)*HS + col)
            = __floats2half2_rn(oacc[nt][2], oacc[nt][3]);
    }
}

// ---------------------------------------------------------------------------
// Launch
// ---------------------------------------------------------------------------
extern "C" void kernel_launch(void* const* d_in, const int* in_sizes, int n_in,
                              void* d_out, int out_size)
{
    const float* hs   = (const float*)d_in[0];
    const float* ehs  = (const float*)d_in[1];
    const float* w_q  = (const float*)d_in[2];
    const float* w_k  = (const float*)d_in[3];
    const float* w_v  = (const float*)d_in[4];
    const float* w_ki = (const float*)d_in[5];
    const float* w_vi = (const float*)d_in[6];
    const float* w_o  = (const float*)d_in[7];
    const float* b_o  = (const float*)d_in[8];
    float* out = (float*)d_out;

    __half *KVq, *Qh, *Ah, *Wh, *Eh, *Wq, *Vtg;
    cudaGetSymbolAddress((void**)&KVq, g_KVq);
    cudaGetSymbolAddress((void**)&Qh,  g_Qh);
    cudaGetSymbolAddress((void**)&Ah,  g_Ah);
    cudaGetSymbolAddress((void**)&Wh,  g_Wh);
    cudaGetSymbolAddress((void**)&Eh,  g_Eh);
    cudaGetSymbolAddress((void**)&Wq,  g_Wq);
    cudaGetSymbolAddress((void**)&Vtg, g_Vt);

    cudaFuncSetAttribute(attn_mma, cudaFuncAttributeMaxDynamicSharedMemorySize, ATT_SMEM);
    cudaFuncSetAttribute(mma_gemm1<HS,false,true>,     cudaFuncAttributeMaxDynamicSharedMemorySize, MMA_SMEM);
    cudaFuncSetAttribute(mma_gemm1<HS,true,false>,     cudaFuncAttributeMaxDynamicSharedMemorySize, MMA_SMEM);
    cudaFuncSetAttribute(mma_gemm1<CROSSD,false,true>, cudaFuncAttributeMaxDynamicSharedMemorySize, MMA_SMEM);

    const int CT = 256;
    dim3 gm(HS/128, MQ/128);   // (10, 256)

    // ---- Q = hidden @ w_q  (fp16 HMMA, fp16 output) ----
    const size_t totA = (size_t)MQ * (HS/4);
    conv_act_h<<<(unsigned)((totA + CT-1)/CT), CT>>>(hs, Ah, totA);
    conv_wt_h<<<dim3(HS/32, HS/32), dim3(32, 8)>>>(w_q, Wh, HS, HS);
    mma_gemm1<HS,false,true><<<gm, 256, MMA_SMEM>>>(Ah, Wh, nullptr, Qh, HS);

    // ---- quad projection (fp16 output) ----
    const size_t totE = (size_t)(BATCH*NCTX) * (CROSSD/4);
    conv_act_h<<<(unsigned)((totE + CT-1)/CT), CT>>>(ehs, Eh, totE);
    conv_wt_h4<<<dim3(HS/32, CROSSD/32, 4), dim3(32, 8)>>>(w_k, w_v, w_ki, w_vi,
                                                           Wq, CROSSD, HS);
    dim3 gq(NQ/128, MEPAD/128);   // (40, 6)
    mma_gemm1<CROSSD,false,true><<<gq, 256, MMA_SMEM>>>(Eh, Wq, nullptr, KVq, NQ);

    // ---- V transpose + out-proj weight conversion ----
    transp_v<<<BATCH*HEADS, 256>>>(KVq, Vtg);
    conv_wt_h<<<dim3(HS/32, HS/32), dim3(32, 8)>>>(w_o, Wh, HS, HS);

    // ---- tensor-core fused dual attention -> fp16 activations ----
    dim3 ga(SEQ/128, HEADS, BATCH);   // (32, 8, 8) = 2048 CTAs
    attn_mma<<<ga, 256, ATT_SMEM>>>(Qh, KVq, Vtg, Ah);

    // ---- out = attn @ w_out + b  (fp16 HMMA, fp32 output) ----
    mma_gemm1<HS,true,false><<<gm, 256, MMA_SMEM>>>(Ah, Wh, b_o, out, HS);
}